// round 10
// baseline (speedup 1.0000x reference)
#include <cuda_runtime.h>
#include <cuda_bf16.h>
#include <cstdint>

#define DM   768
#define NH   12
#define DH   64
#define BB   2
#define TT   4096
#define BH   (BB*NH)
#define MTOT (BB*TT)        // 8192

// ---------------- scratch (__device__ globals; no cudaMalloc allowed) ------
__device__ float g_Q[(size_t)BH*TT*DH];
__device__ float g_K[(size_t)BH*TT*DH];
__device__ float g_V[(size_t)BH*TT*DH];
__device__ float g_att[(size_t)BB*TT*DM];

__device__ __align__(256) __nv_bfloat16 g_xh[(size_t)MTOT*DM];
__device__ __align__(256) __nv_bfloat16 g_xl[(size_t)MTOT*DM];
__device__ __align__(256) __nv_bfloat16 g_wqh[(size_t)3*DM*DM];
__device__ __align__(256) __nv_bfloat16 g_wql[(size_t)3*DM*DM];
__device__ __align__(256) __nv_bfloat16 g_woh[(size_t)DM*DM];
__device__ __align__(256) __nv_bfloat16 g_wol[(size_t)DM*DM];
__device__ __align__(256) __nv_bfloat16 g_ath[(size_t)MTOT*DM];
__device__ __align__(256) __nv_bfloat16 g_atl[(size_t)MTOT*DM];

// ---------------- PTX helpers (sm_80-era: legal on plain sm_103) -----------
__device__ __forceinline__ uint32_t smem_u32(const void* p) {
    uint32_t a;
    asm("{ .reg .u64 t; cvta.to.shared.u64 t, %1; cvt.u32.u64 %0, t; }"
        : "=r"(a) : "l"(p));
    return a;
}
__device__ __forceinline__ void ldmx4(uint32_t* r, uint32_t addr) {
    asm volatile("ldmatrix.sync.aligned.m8n8.x4.shared.b16 {%0,%1,%2,%3}, [%4];"
                 : "=r"(r[0]), "=r"(r[1]), "=r"(r[2]), "=r"(r[3]) : "r"(addr));
}
__device__ __forceinline__ void mma16816(float* c, const uint32_t* a,
                                         const uint32_t* b) {
    asm volatile(
        "mma.sync.aligned.m16n8k16.row.col.f32.bf16.bf16.f32 "
        "{%0,%1,%2,%3}, {%4,%5,%6,%7}, {%8,%9}, {%0,%1,%2,%3};"
        : "+f"(c[0]), "+f"(c[1]), "+f"(c[2]), "+f"(c[3])
        : "r"(a[0]), "r"(a[1]), "r"(a[2]), "r"(a[3]), "r"(b[0]), "r"(b[1]));
}
#define CP16(saddr, gptr) \
    asm volatile("cp.async.cg.shared.global [%0], [%1], 16;" \
                 :: "r"(saddr), "l"(gptr))
#define CPCOMMIT() asm volatile("cp.async.commit_group;" ::: "memory")
#define CPWAIT(n)  asm volatile("cp.async.wait_group %0;" :: "n"(n) : "memory")

// ---------------- fp32 -> bf16 hi/lo split ----------------------------------
__global__ __launch_bounds__(256) void split_kernel(const float* __restrict__ in,
                                                    __nv_bfloat162* __restrict__ hi,
                                                    __nv_bfloat162* __restrict__ lo,
                                                    int n2) {
    int i = blockIdx.x * 256 + threadIdx.x;
    if (i < n2) {
        float2 v = ((const float2*)in)[i];
        __nv_bfloat16 hx = __float2bfloat16(v.x);
        __nv_bfloat16 hy = __float2bfloat16(v.y);
        float rx = v.x - __bfloat162float(hx);
        float ry = v.y - __bfloat162float(hy);
        hi[i] = __halves2bfloat162(hx, hy);
        lo[i] = __halves2bfloat162(__float2bfloat16(rx), __float2bfloat16(ry));
    }
}

// ---------------- HMMA GEMM: C = A @ B^T (+bias) ----------------------------
// A [M x 768] bf16 hi/lo row-major, B [N x 768] bf16 hi/lo row-major.
// CTA 128x128, 8 warps (warp tile 64x32), k-tile 32, double-buffered cp.async.
// 3-term split: C = Ah*Bh + Ah*Bl + Al*Bh.
// MODE 0: qkv scatter into g_Q/g_K/g_V (Q scaled 0.125). MODE 1: dst[m*768+n].
#define KT       32
#define SSTRIDE  40                         // bf16 per smem row (pad: 80 B)
#define TILE_B   (128 * SSTRIDE * 2)        // 10240
#define STAGE_B  (4 * TILE_B)               // 40960
#define GEMM_SMEM (2 * STAGE_B)             // 81920

template <int MODE>
__global__ __launch_bounds__(256) void gemm_mma(const __nv_bfloat16* __restrict__ Ah,
                                                const __nv_bfloat16* __restrict__ Al,
                                                const __nv_bfloat16* __restrict__ Bh,
                                                const __nv_bfloat16* __restrict__ Bl,
                                                const float* __restrict__ bias,
                                                float* __restrict__ dst) {
    extern __shared__ char smem[];
    const uint32_t sb = smem_u32(smem);
    const int tid = threadIdx.x, wid = tid >> 5, lane = tid & 31;
    const int n0 = blockIdx.x * 128, m0 = blockIdx.y * 128;
    const int wm = wid & 1, wn = wid >> 1;           // 2 x 4 warp grid

    // cp.async chunk mapping: per tensor 128 rows x 4 16B-chunks = 512 chunks
    const int r_ld[2]  = { (tid + 0)   >> 2, (tid + 256) >> 2 };
    const int c8_ld[2] = { (tid + 0) & 3,    (tid + 256) & 3 };

    auto issue = [&](int kt, int stage) {
        const int k0 = kt * KT;
        const uint32_t s0 = sb + stage * STAGE_B;
#pragma unroll
        for (int h = 0; h < 2; h++) {
            const int r = r_ld[h], c8 = c8_ld[h];
            const uint32_t so = (uint32_t)(r * (SSTRIDE * 2) + c8 * 16);
            const size_t ga = (size_t)(m0 + r) * DM + k0 + c8 * 8;
            const size_t gb = (size_t)(n0 + r) * DM + k0 + c8 * 8;
            CP16(s0 + 0 * TILE_B + so, Ah + ga);
            CP16(s0 + 1 * TILE_B + so, Al + ga);
            CP16(s0 + 2 * TILE_B + so, Bh + gb);
            CP16(s0 + 3 * TILE_B + so, Bl + gb);
        }
    };

    float C[4][4][4] = {};    // [m16-tile][n8-tile][frag]

    issue(0, 0);
    CPCOMMIT();
    int stage = 0;
    const int NKT = DM / KT;  // 24
    for (int kt = 0; kt < NKT; kt++) {
        if (kt + 1 < NKT) { issue(kt + 1, stage ^ 1); CPCOMMIT(); CPWAIT(1); }
        else              { CPWAIT(0); }
        __syncthreads();

        const uint32_t s0 = sb + stage * STAGE_B;
        // ldmatrix base offsets (lane-dependent)
        const uint32_t aRow = (uint32_t)(wm * 64 + (lane & 15));
        const uint32_t aK   = (uint32_t)((lane >> 4) * 8);
        const uint32_t bRow = (uint32_t)(wn * 32 + (lane & 7) + ((lane >> 4) & 1) * 8);
        const uint32_t bK   = (uint32_t)(((lane >> 3) & 1) * 8);
#pragma unroll
        for (int s = 0; s < 2; s++) {
            uint32_t ah[4][4], al[4][4], bh[2][4], bl[2][4];
#pragma unroll
            for (int mt = 0; mt < 4; mt++) {
                uint32_t off = (aRow + mt * 16) * (SSTRIDE * 2) + (aK + s * 16) * 2;
                ldmx4(ah[mt], s0 + 0 * TILE_B + off);
                ldmx4(al[mt], s0 + 1 * TILE_B + off);
            }
#pragma unroll
            for (int nt = 0; nt < 2; nt++) {
                uint32_t off = (bRow + nt * 16) * (SSTRIDE * 2) + (bK + s * 16) * 2;
                ldmx4(bh[nt], s0 + 2 * TILE_B + off);
                ldmx4(bl[nt], s0 + 3 * TILE_B + off);
            }
#pragma unroll
            for (int mt = 0; mt < 4; mt++) {
#pragma unroll
                for (int nt = 0; nt < 2; nt++) {
#pragma unroll
                    for (int ns = 0; ns < 2; ns++) {
                        float* c = C[mt][nt * 2 + ns];
                        mma16816(c, ah[mt], &bh[nt][ns * 2]);
                        mma16816(c, ah[mt], &bl[nt][ns * 2]);
                        mma16816(c, al[mt], &bh[nt][ns * 2]);
                    }
                }
            }
        }
        __syncthreads();
        stage ^= 1;
    }

    // epilogue: c0,c1 -> (row, col..col+1); c2,c3 -> (row+8, ...)
    const int g = lane >> 2, tg = lane & 3;
#pragma unroll
    for (int mt = 0; mt < 4; mt++) {
#pragma unroll
        for (int n8 = 0; n8 < 4; n8++) {
            const int col = n0 + wn * 32 + n8 * 8 + 2 * tg;
            const int row = m0 + wm * 64 + mt * 16 + g;
            const float b0 = bias[col], b1 = bias[col + 1];
            float* c = C[mt][n8];
            if (MODE == 0) {
                const int which = col / DM;
                const int hd = (col % DM) >> 6;
                const int d0 = col & 63;
                float* dp = (which == 0) ? g_Q : (which == 1) ? g_K : g_V;
                const float sc = (which == 0) ? 0.125f : 1.0f;
#pragma unroll
                for (int hrow = 0; hrow < 2; hrow++) {
                    const int m = row + hrow * 8;
                    const int bb = m >> 12, t = m & 4095;
                    float2 v;
                    v.x = (c[2 * hrow + 0] + b0) * sc;
                    v.y = (c[2 * hrow + 1] + b1) * sc;
                    *(float2*)(dp + (((size_t)(bb * NH + hd)) * TT + t) * DH + d0) = v;
                }
            } else {
#pragma unroll
                for (int hrow = 0; hrow < 2; hrow++) {
                    const int m = row + hrow * 8;
                    float2 v;
                    v.x = c[2 * hrow + 0] + b0;
                    v.y = c[2 * hrow + 1] + b1;
                    *(float2*)(dst + (size_t)m * DM + col) = v;
                }
            }
        }
    }
}

// ---------------------------------------------------------------------------
// Flash attention (round-4 best): 128q x 128k, 256 threads, 8x8 fragments.
// ---------------------------------------------------------------------------
__global__ __launch_bounds__(256) void attn_kernel(const int* __restrict__ mask,
                                                   float* __restrict__ att) {
    extern __shared__ float sm[];
    float* Qt = sm;                    // [64][128]  d-major
    float* Kt = Qt + 64 * 128;         // [64][128]  d-major
    float* Vs = Kt + 64 * 128;         // [128][64]  k-major
    float* Pt = Vs + 128 * 64;         // [128][132] q-major, padded
    float* alpha_s = Pt + 128 * 132;   // [128]

    const int tid = threadIdx.x;
    const int tx = tid & 15, ty = tid >> 4;   // S mapping
    const int dx = tid & 7,  ro = tid >> 3;   // PV mapping
    const int bh = blockIdx.y;
    const int b = bh / NH, head = bh % NH;
    const int q0 = blockIdx.x * 128;

    const float* Qp = g_Q + (size_t)bh * TT * DH;
    const float* Kp = g_K + (size_t)bh * TT * DH;
    const float* Vp = g_V + (size_t)bh * TT * DH;
    const int* mrow_g = mask + (size_t)b * TT;

    {
        int r = tid >> 2, d0 = (tid & 3) * 16;
#pragma unroll
        for (int h = 0; h < 2; h++) {
            int rr = r + 64 * h;
            const float* src = Qp + (size_t)(q0 + rr) * DH + d0;
#pragma unroll
            for (int u = 0; u < 4; u++) {
                float4 v = *(const float4*)(src + 4 * u);
                Qt[(d0 + 4 * u + 0) * 128 + rr] = v.x;
                Qt[(d0 + 4 * u + 1) * 128 + rr] = v.y;
                Qt[(d0 + 4 * u + 2) * 128 + rr] = v.z;
                Qt[(d0 + 4 * u + 3) * 128 + rr] = v.w;
            }
        }
    }

    float O[4][8] = {};
    float mr[8], lw[8];
#pragma unroll
    for (int i = 0; i < 8; i++) { mr[i] = -1e30f; lw[i] = 0.f; }

    for (int jt = 0; jt < TT / 128; jt++) {
        __syncthreads();
        {
            int r = tid >> 2, d0 = (tid & 3) * 16;
#pragma unroll
            for (int h = 0; h < 2; h++) {
                int rr = r + 64 * h;
                const float* ks = Kp + (size_t)(jt * 128 + rr) * DH + d0;
                const float* vs = Vp + (size_t)(jt * 128 + rr) * DH + d0;
#pragma unroll
                for (int u = 0; u < 4; u++) {
                    float4 kv = *(const float4*)(ks + 4 * u);
                    Kt[(d0 + 4 * u + 0) * 128 + rr] = kv.x;
                    Kt[(d0 + 4 * u + 1) * 128 + rr] = kv.y;
                    Kt[(d0 + 4 * u + 2) * 128 + rr] = kv.z;
                    Kt[(d0 + 4 * u + 3) * 128 + rr] = kv.w;
                    *(float4*)&Vs[rr * 64 + d0 + 4 * u] = *(const float4*)(vs + 4 * u);
                }
            }
        }
        int msk[8];
        {
            const int* mp = mrow_g + jt * 128 + 8 * tx;
            *(int4*)&msk[0] = *(const int4*)mp;
            *(int4*)&msk[4] = *(const int4*)(mp + 4);
        }
        __syncthreads();

        float s[8][8] = {};
#pragma unroll 8
        for (int d = 0; d < 64; d++) {
            float q[8], k[8];
            *(float4*)&q[0] = *(const float4*)&Qt[d * 128 + 8 * ty];
            *(float4*)&q[4] = *(const float4*)&Qt[d * 128 + 8 * ty + 4];
            *(float4*)&k[0] = *(const float4*)&Kt[d * 128 + 8 * tx];
            *(float4*)&k[4] = *(const float4*)&Kt[d * 128 + 8 * tx + 4];
#pragma unroll
            for (int i = 0; i < 8; i++)
#pragma unroll
                for (int j = 0; j < 8; j++)
                    s[i][j] += q[i] * k[j];
        }
#pragma unroll
        for (int j = 0; j < 8; j++) {
            if (msk[j] == 0) {
#pragma unroll
                for (int i = 0; i < 8; i++) s[i][j] = -1e9f;
            }
        }

#pragma unroll
        for (int i = 0; i < 8; i++) {
            float mx = s[i][0];
#pragma unroll
            for (int j = 1; j < 8; j++) mx = fmaxf(mx, s[i][j]);
            mx = fmaxf(mx, __shfl_xor_sync(0xffffffffu, mx, 1));
            mx = fmaxf(mx, __shfl_xor_sync(0xffffffffu, mx, 2));
            mx = fmaxf(mx, __shfl_xor_sync(0xffffffffu, mx, 4));
            mx = fmaxf(mx, __shfl_xor_sync(0xffffffffu, mx, 8));
            float mnew = fmaxf(mr[i], mx);
            float al = __expf(mr[i] - mnew);
            float sum = 0.f;
#pragma unroll
            for (int j = 0; j < 8; j++) {
                s[i][j] = __expf(s[i][j] - mnew);
                sum += s[i][j];
            }
            sum += __shfl_xor_sync(0xffffffffu, sum, 1);
            sum += __shfl_xor_sync(0xffffffffu, sum, 2);
            sum += __shfl_xor_sync(0xffffffffu, sum, 4);
            sum += __shfl_xor_sync(0xffffffffu, sum, 8);
            lw[i] = lw[i] * al + sum;
            mr[i] = mnew;
            if (tx == 0) alpha_s[8 * ty + i] = al;
            float* prow = &Pt[(8 * ty + i) * 132 + 8 * tx];
            *(float4*)prow       = make_float4(s[i][0], s[i][1], s[i][2], s[i][3]);
            *(float4*)(prow + 4) = make_float4(s[i][4], s[i][5], s[i][6], s[i][7]);
        }
        __syncthreads();

        float al4[4];
#pragma unroll
        for (int i = 0; i < 4; i++) al4[i] = alpha_s[ro + 32 * i];
#pragma unroll
        for (int i = 0; i < 4; i++)
#pragma unroll
            for (int j = 0; j < 8; j++) O[i][j] *= al4[i];

#pragma unroll 2
        for (int k4 = 0; k4 < 128; k4 += 4) {
            float p[4][4];
#pragma unroll
            for (int i = 0; i < 4; i++)
                *(float4*)p[i] = *(const float4*)&Pt[(ro + 32 * i) * 132 + k4];
#pragma unroll
            for (int u = 0; u < 4; u++) {
                float v[8];
                *(float4*)&v[0] = *(const float4*)&Vs[(k4 + u) * 64 + 8 * dx];
                *(float4*)&v[4] = *(const float4*)&Vs[(k4 + u) * 64 + 8 * dx + 4];
#pragma unroll
                for (int i = 0; i < 4; i++)
#pragma unroll
                    for (int j = 0; j < 8; j++)
                        O[i][j] += p[i][u] * v[j];
            }
        }
    }

    __syncthreads();
    if (tx == 0) {
#pragma unroll
        for (int i = 0; i < 8; i++) alpha_s[8 * ty + i] = 1.0f / lw[i];
    }
    __syncthreads();
#pragma unroll
    for (int i = 0; i < 4; i++) {
        float inv = alpha_s[ro + 32 * i];
        int t = q0 + ro + 32 * i;
        float* o = att + (((size_t)b * TT + t) * NH + head) * DH + 8 * dx;
        float4 v0, v1;
        v0.x = O[i][0] * inv; v0.y = O[i][1] * inv;
        v0.z = O[i][2] * inv; v0.w = O[i][3] * inv;
        v1.x = O[i][4] * inv; v1.y = O[i][5] * inv;
        v1.z = O[i][6] * inv; v1.w = O[i][7] * inv;
        *(float4*)o = v0;
        *(float4*)(o + 4) = v1;
    }
}

// ---------------------------------------------------------------------------
// Inputs (metadata order): x, w_qkv, b_qkv, w_out, b_out, mask. Output: float32.
// ---------------------------------------------------------------------------
extern "C" void kernel_launch(void* const* d_in, const int* in_sizes, int n_in,
                              void* d_out, int out_size) {
    const float* x     = (const float*)d_in[0];
    const float* w_qkv = (const float*)d_in[1];
    const float* b_qkv = (const float*)d_in[2];
    const float* w_out = (const float*)d_in[3];
    const float* b_out = (const float*)d_in[4];
    const int*   mask  = (const int*)d_in[5];
    float* out = (float*)d_out;

    static const size_t ATTN_SMEM =
        (2 * 64 * 128 + 128 * 64 + 128 * 132 + 128) * sizeof(float); // 166912 B
    cudaFuncSetAttribute(attn_kernel, cudaFuncAttributeMaxDynamicSharedMemorySize,
                         (int)ATTN_SMEM);
    cudaFuncSetAttribute(gemm_mma<0>, cudaFuncAttributeMaxDynamicSharedMemorySize,
                         GEMM_SMEM);
    cudaFuncSetAttribute(gemm_mma<1>, cudaFuncAttributeMaxDynamicSharedMemorySize,
                         GEMM_SMEM);

    float* att;   cudaGetSymbolAddress((void**)&att, g_att);
    __nv_bfloat16 *xh, *xl, *wqh, *wql, *woh, *wol, *ath, *atl;
    cudaGetSymbolAddress((void**)&xh,  g_xh);
    cudaGetSymbolAddress((void**)&xl,  g_xl);
    cudaGetSymbolAddress((void**)&wqh, g_wqh);
    cudaGetSymbolAddress((void**)&wql, g_wql);
    cudaGetSymbolAddress((void**)&woh, g_woh);
    cudaGetSymbolAddress((void**)&wol, g_wol);
    cudaGetSymbolAddress((void**)&ath, g_ath);
    cudaGetSymbolAddress((void**)&atl, g_atl);

    // split inputs to bf16 hi/lo
    int nx = MTOT * DM / 2, nq = 3 * DM * DM / 2, no = DM * DM / 2;
    split_kernel<<<(nx + 255) / 256, 256>>>(x, (__nv_bfloat162*)xh,
                                            (__nv_bfloat162*)xl, nx);
    split_kernel<<<(nq + 255) / 256, 256>>>(w_qkv, (__nv_bfloat162*)wqh,
                                            (__nv_bfloat162*)wql, nq);
    split_kernel<<<(no + 255) / 256, 256>>>(w_out, (__nv_bfloat162*)woh,
                                            (__nv_bfloat162*)wol, no);

    // QKV projection on tensor cores (HMMA)
    gemm_mma<0><<<dim3(3 * DM / 128, MTOT / 128), 256, GEMM_SMEM>>>(
        xh, xl, wqh, wql, b_qkv, nullptr);

    // attention (fp32 CUDA cores, round-4 version)
    attn_kernel<<<dim3(TT / 128, BH), 256, ATTN_SMEM>>>(mask, att);

    // split attention output, then out-projection on tensor cores
    split_kernel<<<(nx + 255) / 256, 256>>>(att, (__nv_bfloat162*)ath,
                                            (__nv_bfloat162*)atl, nx);
    gemm_mma<1><<<dim3(DM / 128, MTOT / 128), 256, GEMM_SMEM>>>(
        ath, atl, woh, wol, b_out, out);
}

// round 11
// speedup vs baseline: 2.5456x; 2.5456x over previous
#include <cuda_runtime.h>
#include <cuda_bf16.h>
#include <cstdint>

#define DM   768
#define NH   12
#define DH   64
#define BB   2
#define TT   4096
#define BH   (BB*NH)
#define MTOT (BB*TT)        // 8192

// ---------------- scratch (__device__ globals; no cudaMalloc allowed) ------
__device__ __align__(256) __nv_bfloat16 g_Qh[(size_t)BH*TT*DH];
__device__ __align__(256) __nv_bfloat16 g_Ql[(size_t)BH*TT*DH];
__device__ __align__(256) __nv_bfloat16 g_Kh[(size_t)BH*TT*DH];
__device__ __align__(256) __nv_bfloat16 g_Kl[(size_t)BH*TT*DH];
__device__ __align__(256) __nv_bfloat16 g_Vh[(size_t)BH*TT*DH];
__device__ __align__(256) __nv_bfloat16 g_Vl[(size_t)BH*TT*DH];

__device__ __align__(256) __nv_bfloat16 g_xh[(size_t)MTOT*DM];
__device__ __align__(256) __nv_bfloat16 g_xl[(size_t)MTOT*DM];
__device__ __align__(256) __nv_bfloat16 g_wqh[(size_t)3*DM*DM];
__device__ __align__(256) __nv_bfloat16 g_wql[(size_t)3*DM*DM];
__device__ __align__(256) __nv_bfloat16 g_woh[(size_t)DM*DM];
__device__ __align__(256) __nv_bfloat16 g_wol[(size_t)DM*DM];
__device__ __align__(256) __nv_bfloat16 g_ath[(size_t)MTOT*DM];
__device__ __align__(256) __nv_bfloat16 g_atl[(size_t)MTOT*DM];

// ---------------- PTX helpers (sm_80-era: legal on plain sm_103) -----------
__device__ __forceinline__ uint32_t smem_u32(const void* p) {
    uint32_t a;
    asm("{ .reg .u64 t; cvta.to.shared.u64 t, %1; cvt.u32.u64 %0, t; }"
        : "=r"(a) : "l"(p));
    return a;
}
__device__ __forceinline__ void ldmx4(uint32_t* r, uint32_t addr) {
    asm volatile("ldmatrix.sync.aligned.m8n8.x4.shared.b16 {%0,%1,%2,%3}, [%4];"
                 : "=r"(r[0]), "=r"(r[1]), "=r"(r[2]), "=r"(r[3]) : "r"(addr));
}
__device__ __forceinline__ void ldmx4t(uint32_t* r, uint32_t addr) {
    asm volatile("ldmatrix.sync.aligned.m8n8.x4.trans.shared.b16 {%0,%1,%2,%3}, [%4];"
                 : "=r"(r[0]), "=r"(r[1]), "=r"(r[2]), "=r"(r[3]) : "r"(addr));
}
__device__ __forceinline__ void mma16816(float* c, const uint32_t* a,
                                         const uint32_t* b) {
    asm volatile(
        "mma.sync.aligned.m16n8k16.row.col.f32.bf16.bf16.f32 "
        "{%0,%1,%2,%3}, {%4,%5,%6,%7}, {%8,%9}, {%0,%1,%2,%3};"
        : "+f"(c[0]), "+f"(c[1]), "+f"(c[2]), "+f"(c[3])
        : "r"(a[0]), "r"(a[1]), "r"(a[2]), "r"(a[3]), "r"(b[0]), "r"(b[1]));
}
#define CP16(saddr, gptr) \
    asm volatile("cp.async.cg.shared.global [%0], [%1], 16;" \
                 :: "r"(saddr), "l"(gptr))
#define CPCOMMIT() asm volatile("cp.async.commit_group;" ::: "memory")
#define CPWAIT(n)  asm volatile("cp.async.wait_group %0;" :: "n"(n) : "memory")

// MUFU-free exp: magic-number round + degree-6 2^f polynomial (rel err ~2e-7)
__device__ __forceinline__ float fexp(float x) {
    x = fmaxf(x, -80.0f);
    float y = x * 1.4426950408889634f;
    float t = y + 12582912.0f;                 // 1.5*2^23 round-to-nearest
    int   n = __float_as_int(t) - 0x4B400000;
    float f = y - (t - 12582912.0f);           // f in [-0.5, 0.5]
    float p =            1.5403530e-4f;
    p = fmaf(p, f, 1.3333558e-3f);
    p = fmaf(p, f, 9.6181291e-3f);
    p = fmaf(p, f, 5.5504109e-2f);
    p = fmaf(p, f, 2.4022651e-1f);
    p = fmaf(p, f, 6.9314718e-1f);
    p = fmaf(p, f, 1.0f);
    return __int_as_float(__float_as_int(p) + (n << 23));
}

// ---------------- fp32 -> bf16 hi/lo split ----------------------------------
__global__ __launch_bounds__(256) void split_kernel(const float* __restrict__ in,
                                                    __nv_bfloat162* __restrict__ hi,
                                                    __nv_bfloat162* __restrict__ lo,
                                                    int n2) {
    int i = blockIdx.x * 256 + threadIdx.x;
    if (i < n2) {
        float2 v = ((const float2*)in)[i];
        __nv_bfloat16 hx = __float2bfloat16(v.x);
        __nv_bfloat16 hy = __float2bfloat16(v.y);
        float rx = v.x - __bfloat162float(hx);
        float ry = v.y - __bfloat162float(hy);
        hi[i] = __halves2bfloat162(hx, hy);
        lo[i] = __halves2bfloat162(__float2bfloat16(rx), __float2bfloat16(ry));
    }
}

// ---------------- HMMA GEMM: C = A @ B^T (+bias) ----------------------------
// MODE 0: qkv -> scatter bf16 hi/lo into g_Q*/g_K*/g_V* (Q scaled 0.125).
// MODE 1: out -> fp32 dst[m*768+n].
#define KT       32
#define SSTRIDE  40
#define TILE_B   (128 * SSTRIDE * 2)
#define STAGE_B  (4 * TILE_B)
#define GEMM_SMEM (2 * STAGE_B)

template <int MODE>
__global__ __launch_bounds__(256) void gemm_mma(const __nv_bfloat16* __restrict__ Ah,
                                                const __nv_bfloat16* __restrict__ Al,
                                                const __nv_bfloat16* __restrict__ Bh,
                                                const __nv_bfloat16* __restrict__ Bl,
                                                const float* __restrict__ bias,
                                                float* __restrict__ dst) {
    extern __shared__ char smem[];
    const uint32_t sb = smem_u32(smem);
    const int tid = threadIdx.x, wid = tid >> 5, lane = tid & 31;
    const int n0 = blockIdx.x * 128, m0 = blockIdx.y * 128;
    const int wm = wid & 1, wn = wid >> 1;

    const int r_ld[2]  = { (tid + 0)   >> 2, (tid + 256) >> 2 };
    const int c8_ld[2] = { (tid + 0) & 3,    (tid + 256) & 3 };

    auto issue = [&](int kt, int stage) {
        const int k0 = kt * KT;
        const uint32_t s0 = sb + stage * STAGE_B;
#pragma unroll
        for (int h = 0; h < 2; h++) {
            const int r = r_ld[h], c8 = c8_ld[h];
            const uint32_t so = (uint32_t)(r * (SSTRIDE * 2) + c8 * 16);
            const size_t ga = (size_t)(m0 + r) * DM + k0 + c8 * 8;
            const size_t gb = (size_t)(n0 + r) * DM + k0 + c8 * 8;
            CP16(s0 + 0 * TILE_B + so, Ah + ga);
            CP16(s0 + 1 * TILE_B + so, Al + ga);
            CP16(s0 + 2 * TILE_B + so, Bh + gb);
            CP16(s0 + 3 * TILE_B + so, Bl + gb);
        }
    };

    float C[4][4][4] = {};

    issue(0, 0);
    CPCOMMIT();
    int stage = 0;
    const int NKT = DM / KT;
    for (int kt = 0; kt < NKT; kt++) {
        if (kt + 1 < NKT) { issue(kt + 1, stage ^ 1); CPCOMMIT(); CPWAIT(1); }
        else              { CPWAIT(0); }
        __syncthreads();

        const uint32_t s0 = sb + stage * STAGE_B;
        const uint32_t aRow = (uint32_t)(wm * 64 + (lane & 15));
        const uint32_t aK   = (uint32_t)((lane >> 4) * 8);
        const uint32_t bRow = (uint32_t)(wn * 32 + (lane & 7) + ((lane >> 4) & 1) * 8);
        const uint32_t bK   = (uint32_t)(((lane >> 3) & 1) * 8);
#pragma unroll
        for (int s = 0; s < 2; s++) {
            uint32_t ah[4][4], al[4][4], bh[2][4], bl[2][4];
#pragma unroll
            for (int mt = 0; mt < 4; mt++) {
                uint32_t off = (aRow + mt * 16) * (SSTRIDE * 2) + (aK + s * 16) * 2;
                ldmx4(ah[mt], s0 + 0 * TILE_B + off);
                ldmx4(al[mt], s0 + 1 * TILE_B + off);
            }
#pragma unroll
            for (int nt = 0; nt < 2; nt++) {
                uint32_t off = (bRow + nt * 16) * (SSTRIDE * 2) + (bK + s * 16) * 2;
                ldmx4(bh[nt], s0 + 2 * TILE_B + off);
                ldmx4(bl[nt], s0 + 3 * TILE_B + off);
            }
#pragma unroll
            for (int mt = 0; mt < 4; mt++) {
#pragma unroll
                for (int nt = 0; nt < 2; nt++) {
#pragma unroll
                    for (int ns = 0; ns < 2; ns++) {
                        float* c = C[mt][nt * 2 + ns];
                        mma16816(c, ah[mt], &bh[nt][ns * 2]);
                        mma16816(c, ah[mt], &bl[nt][ns * 2]);
                        mma16816(c, al[mt], &bh[nt][ns * 2]);
                    }
                }
            }
        }
        __syncthreads();
        stage ^= 1;
    }

    const int g = lane >> 2, tg = lane & 3;
#pragma unroll
    for (int mt = 0; mt < 4; mt++) {
#pragma unroll
        for (int n8 = 0; n8 < 4; n8++) {
            const int col = n0 + wn * 32 + n8 * 8 + 2 * tg;
            const int row = m0 + wm * 64 + mt * 16 + g;
            const float b0 = bias[col], b1 = bias[col + 1];
            float* c = C[mt][n8];
            if (MODE == 0) {
                const int which = col / DM;
                const int hd = (col % DM) >> 6;
                const int d0 = col & 63;
                __nv_bfloat16 *dph, *dpl;
                if (which == 0)      { dph = g_Qh; dpl = g_Ql; }
                else if (which == 1) { dph = g_Kh; dpl = g_Kl; }
                else                 { dph = g_Vh; dpl = g_Vl; }
                const float sc = (which == 0) ? 0.125f : 1.0f;
#pragma unroll
                for (int hrow = 0; hrow < 2; hrow++) {
                    const int m = row + hrow * 8;
                    const int bb = m >> 12, t = m & 4095;
                    const size_t idx = (((size_t)(bb * NH + hd)) * TT + t) * DH + d0;
                    float v0 = (c[2 * hrow + 0] + b0) * sc;
                    float v1 = (c[2 * hrow + 1] + b1) * sc;
                    __nv_bfloat162 h2 = __floats2bfloat162_rn(v0, v1);
                    float2 hf = __bfloat1622float2(h2);
                    __nv_bfloat162 l2 = __floats2bfloat162_rn(v0 - hf.x, v1 - hf.y);
                    *(__nv_bfloat162*)(dph + idx) = h2;
                    *(__nv_bfloat162*)(dpl + idx) = l2;
                }
            } else {
#pragma unroll
                for (int hrow = 0; hrow < 2; hrow++) {
                    const int m = row + hrow * 8;
                    float2 v;
                    v.x = c[2 * hrow + 0] + b0;
                    v.y = c[2 * hrow + 1] + b1;
                    *(float2*)(dst + (size_t)m * DM + col) = v;
                }
            }
        }
    }
}

// ---------------- HMMA flash attention --------------------------------------
// CTA = 128 q-rows x one (b,h); 8 warps, each owns 16 q-rows (full k width).
// K-tile 128. S = QhKh+QhKl+QlKh (fp32 acc). Softmax with FMA-poly exp (no
// MUFU). P fragments pass register-direct into PV (Ph,Pl). PV adds VhVl split.
// K/V hi/lo double-buffered via cp.async. Output written bf16 hi/lo for the
// out-projection GEMM.
#define AST      72                       // bf16 stride (144 B rows)
#define ATILE_B  (128 * AST * 2)          // 18432 B per tensor tile
#define ASTAGE_B (4 * ATILE_B)            // K/V hi/lo = 73728 B
#define AMASK_OFF (2 * ASTAGE_B)          // 147456
#define ATT_SMEM  (AMASK_OFF + TT * 4)    // +16 KB mask floats = 163840

__global__ __launch_bounds__(256) void attn_mma(const int* __restrict__ mask) {
    extern __shared__ char smraw[];
    const uint32_t sb = smem_u32(smraw);
    float* mskf = (float*)(smraw + AMASK_OFF);

    const int tid = threadIdx.x, w = tid >> 5, lane = tid & 31;
    const int bh = blockIdx.y, b = bh / NH, head = bh % NH;
    const int q0 = blockIdx.x * 128;
    const size_t kvbase = (size_t)bh * TT * DH;

    // mask -> additive floats (whole row, once)
    for (int i = tid; i < TT / 4; i += 256) {
        int4 mm = ((const int4*)(mask + (size_t)b * TT))[i];
        float4 f;
        f.x = mm.x ? 0.f : -1e9f; f.y = mm.y ? 0.f : -1e9f;
        f.z = mm.z ? 0.f : -1e9f; f.w = mm.w ? 0.f : -1e9f;
        ((float4*)mskf)[i] = f;
    }

    // stage Q (hi/lo) into stage-0 K buffers, extract fragments to registers
    {
        const size_t qb = kvbase + (size_t)q0 * DH;
#pragma unroll
        for (int h = 0; h < 4; h++) {
            int c = tid + h * 256;
            int r = c >> 3, k8 = c & 7;
            uint32_t so = r * 144 + k8 * 16;
            CP16(sb + so,           g_Qh + qb + r * 64 + k8 * 8);
            CP16(sb + ATILE_B + so, g_Ql + qb + r * 64 + k8 * 8);
        }
        CPCOMMIT(); CPWAIT(0);
    }
    __syncthreads();
    uint32_t aQh[4][4], aQl[4][4];
    {
        uint32_t row = 16 * w + (lane & 15);
#pragma unroll
        for (int ks = 0; ks < 4; ks++) {
            uint32_t off = row * 144 + (2 * ks + (lane >> 4)) * 16;
            ldmx4(aQh[ks], sb + off);
            ldmx4(aQl[ks], sb + ATILE_B + off);
        }
    }
    __syncthreads();

    auto issue = [&](int jt, int s) {
        const size_t gbase = kvbase + (size_t)jt * 128 * DH;
        const uint32_t s0 = sb + s * ASTAGE_B;
#pragma unroll
        for (int h = 0; h < 4; h++) {
            int c = tid + h * 256;
            int r = c >> 3, k8 = c & 7;
            uint32_t so = r * 144 + k8 * 16;
            size_t gg = gbase + r * 64 + k8 * 8;
            CP16(s0 + 0 * ATILE_B + so, g_Kh + gg);
            CP16(s0 + 1 * ATILE_B + so, g_Kl + gg);
            CP16(s0 + 2 * ATILE_B + so, g_Vh + gg);
            CP16(s0 + 3 * ATILE_B + so, g_Vl + gg);
        }
    };

    issue(0, 0); CPCOMMIT();

    float O[8][4] = {};
    float mr0 = -1e30f, mr1 = -1e30f, lw0 = 0.f, lw1 = 0.f;
    int stage = 0;

    const uint32_t bRow = (lane & 7) + ((lane >> 4) << 3);       // K frag rows
    const uint32_t bCs  = (lane >> 3) & 1;                       // K chunk sel
    const uint32_t vRow = (lane & 7) + (((lane >> 3) & 1) << 3); // V frag rows
    const uint32_t vCs  = lane >> 4;                             // V chunk sel

    for (int jt = 0; jt < TT / 128; jt++) {
        if (jt + 1 < TT / 128) { issue(jt + 1, stage ^ 1); CPCOMMIT(); CPWAIT(1); }
        else                   { CPWAIT(0); }
        __syncthreads();
        const uint32_t s0 = sb + stage * ASTAGE_B;
        const uint32_t sKh = s0, sKl = s0 + ATILE_B;
        const uint32_t sVh = s0 + 2 * ATILE_B, sVl = s0 + 3 * ATILE_B;

        // ---- S = Q @ K^T (3-term split) ----
        float Cs[16][4] = {};
#pragma unroll
        for (int ks = 0; ks < 4; ks++) {
#pragma unroll
            for (int nt = 0; nt < 8; nt++) {
                uint32_t off = (16 * nt + bRow) * 144 + (2 * ks + bCs) * 16;
                uint32_t kh4[4], kl4[4];
                ldmx4(kh4, sKh + off);
                ldmx4(kl4, sKl + off);
                mma16816(Cs[2 * nt],     aQh[ks], &kh4[0]);
                mma16816(Cs[2 * nt],     aQh[ks], &kl4[0]);
                mma16816(Cs[2 * nt],     aQl[ks], &kh4[0]);
                mma16816(Cs[2 * nt + 1], aQh[ks], &kh4[2]);
                mma16816(Cs[2 * nt + 1], aQh[ks], &kl4[2]);
                mma16816(Cs[2 * nt + 1], aQl[ks], &kh4[2]);
            }
        }

        // ---- mask + online softmax (rows r=lane/4 and r+8 of this warp) ----
        const int colb = jt * 128 + 2 * (lane & 3);
        float mx0 = -1e30f, mx1 = -1e30f;
#pragma unroll
        for (int t = 0; t < 16; t++) {
            float2 mk = *(const float2*)&mskf[colb + 8 * t - jt * 128 + jt * 128];
            mk = *(const float2*)&mskf[jt * 128 + 8 * t + 2 * (lane & 3)];
            Cs[t][0] += mk.x; Cs[t][1] += mk.y;
            Cs[t][2] += mk.x; Cs[t][3] += mk.y;
            mx0 = fmaxf(mx0, fmaxf(Cs[t][0], Cs[t][1]));
            mx1 = fmaxf(mx1, fmaxf(Cs[t][2], Cs[t][3]));
        }
        mx0 = fmaxf(mx0, __shfl_xor_sync(0xffffffffu, mx0, 1));
        mx0 = fmaxf(mx0, __shfl_xor_sync(0xffffffffu, mx0, 2));
        mx1 = fmaxf(mx1, __shfl_xor_sync(0xffffffffu, mx1, 1));
        mx1 = fmaxf(mx1, __shfl_xor_sync(0xffffffffu, mx1, 2));
        float mn0 = fmaxf(mr0, mx0), mn1 = fmaxf(mr1, mx1);
        float al0 = fexp(mr0 - mn0), al1 = fexp(mr1 - mn1);

        uint32_t ph0[16], ph1[16], pl0[16], pl1[16];
        float sum0 = 0.f, sum1 = 0.f;
#pragma unroll
        for (int t = 0; t < 16; t++) {
            float p0 = fexp(Cs[t][0] - mn0);
            float p1 = fexp(Cs[t][1] - mn0);
            float p2 = fexp(Cs[t][2] - mn1);
            float p3 = fexp(Cs[t][3] - mn1);
            sum0 += p0 + p1; sum1 += p2 + p3;
            __nv_bfloat162 h01 = __floats2bfloat162_rn(p0, p1);
            __nv_bfloat162 h23 = __floats2bfloat162_rn(p2, p3);
            float2 f01 = __bfloat1622float2(h01);
            float2 f23 = __bfloat1622float2(h23);
            __nv_bfloat162 l01 = __floats2bfloat162_rn(p0 - f01.x, p1 - f01.y);
            __nv_bfloat162 l23 = __floats2bfloat162_rn(p2 - f23.x, p3 - f23.y);
            ph0[t] = *(uint32_t*)&h01; ph1[t] = *(uint32_t*)&h23;
            pl0[t] = *(uint32_t*)&l01; pl1[t] = *(uint32_t*)&l23;
        }
        sum0 += __shfl_xor_sync(0xffffffffu, sum0, 1);
        sum0 += __shfl_xor_sync(0xffffffffu, sum0, 2);
        sum1 += __shfl_xor_sync(0xffffffffu, sum1, 1);
        sum1 += __shfl_xor_sync(0xffffffffu, sum1, 2);
        lw0 = lw0 * al0 + sum0;  lw1 = lw1 * al1 + sum1;
        mr0 = mn0;  mr1 = mn1;

        // ---- O = O*alpha + P @ V (3-term split) ----
#pragma unroll
        for (int dt = 0; dt < 8; dt++) {
            O[dt][0] *= al0; O[dt][1] *= al0;
            O[dt][2] *= al1; O[dt][3] *= al1;
        }
#pragma unroll
        for (int j = 0; j < 8; j++) {
            uint32_t Ahh[4] = { ph0[2 * j], ph1[2 * j], ph0[2 * j + 1], ph1[2 * j + 1] };
            uint32_t All[4] = { pl0[2 * j], pl1[2 * j], pl0[2 * j + 1], pl1[2 * j + 1] };
#pragma unroll
            for (int dp = 0; dp < 4; dp++) {
                uint32_t off = (16 * j + vRow) * 144 + (2 * dp + vCs) * 16;
                uint32_t vh4[4], vl4[4];
                ldmx4t(vh4, sVh + off);
                ldmx4t(vl4, sVl + off);
                mma16816(O[2 * dp],     Ahh, &vh4[0]);
                mma16816(O[2 * dp],     Ahh, &vl4[0]);
                mma16816(O[2 * dp],     All, &vh4[0]);
                mma16816(O[2 * dp + 1], Ahh, &vh4[2]);
                mma16816(O[2 * dp + 1], Ahh, &vl4[2]);
                mma16816(O[2 * dp + 1], All, &vh4[2]);
            }
        }
        __syncthreads();
        stage ^= 1;
    }

    // ---- epilogue: normalize, write bf16 hi/lo att in [B,T,H*Dh] ----------
    float inv0 = 1.0f / lw0, inv1 = 1.0f / lw1;
    const int t_lo = q0 + 16 * w + (lane >> 2);
    const size_t m_lo = (size_t)b * TT + t_lo;
#pragma unroll
    for (int dt = 0; dt < 8; dt++) {
        const int col = head * 64 + 8 * dt + 2 * (lane & 3);
#pragma unroll
        for (int hrow = 0; hrow < 2; hrow++) {
            const size_t idx = (m_lo + hrow * 8) * DM + col;
            float v0 = O[dt][2 * hrow + 0] * (hrow ? inv1 : inv0);
            float v1 = O[dt][2 * hrow + 1] * (hrow ? inv1 : inv0);
            __nv_bfloat162 h2 = __floats2bfloat162_rn(v0, v1);
            float2 hf = __bfloat1622float2(h2);
            __nv_bfloat162 l2 = __floats2bfloat162_rn(v0 - hf.x, v1 - hf.y);
            *(__nv_bfloat162*)(g_ath + idx) = h2;
            *(__nv_bfloat162*)(g_atl + idx) = l2;
        }
    }
}

// ---------------------------------------------------------------------------
// Inputs (metadata order): x, w_qkv, b_qkv, w_out, b_out, mask. Output: float32.
// ---------------------------------------------------------------------------
extern "C" void kernel_launch(void* const* d_in, const int* in_sizes, int n_in,
                              void* d_out, int out_size) {
    const float* x     = (const float*)d_in[0];
    const float* w_qkv = (const float*)d_in[1];
    const float* b_qkv = (const float*)d_in[2];
    const float* w_out = (const float*)d_in[3];
    const float* b_out = (const float*)d_in[4];
    const int*   mask  = (const int*)d_in[5];
    float* out = (float*)d_out;

    cudaFuncSetAttribute(gemm_mma<0>, cudaFuncAttributeMaxDynamicSharedMemorySize,
                         GEMM_SMEM);
    cudaFuncSetAttribute(gemm_mma<1>, cudaFuncAttributeMaxDynamicSharedMemorySize,
                         GEMM_SMEM);
    cudaFuncSetAttribute(attn_mma, cudaFuncAttributeMaxDynamicSharedMemorySize,
                         ATT_SMEM);

    __nv_bfloat16 *xh, *xl, *wqh, *wql, *woh, *wol, *ath, *atl;
    cudaGetSymbolAddress((void**)&xh,  g_xh);
    cudaGetSymbolAddress((void**)&xl,  g_xl);
    cudaGetSymbolAddress((void**)&wqh, g_wqh);
    cudaGetSymbolAddress((void**)&wql, g_wql);
    cudaGetSymbolAddress((void**)&woh, g_woh);
    cudaGetSymbolAddress((void**)&wol, g_wol);
    cudaGetSymbolAddress((void**)&ath, g_ath);
    cudaGetSymbolAddress((void**)&atl, g_atl);

    int nx = MTOT * DM / 2, nq = 3 * DM * DM / 2, no = DM * DM / 2;
    split_kernel<<<(nx + 255) / 256, 256>>>(x, (__nv_bfloat162*)xh,
                                            (__nv_bfloat162*)xl, nx);
    split_kernel<<<(nq + 255) / 256, 256>>>(w_qkv, (__nv_bfloat162*)wqh,
                                            (__nv_bfloat162*)wql, nq);
    split_kernel<<<(no + 255) / 256, 256>>>(w_out, (__nv_bfloat162*)woh,
                                            (__nv_bfloat162*)wol, no);

    // QKV projection (HMMA) -> bf16 hi/lo Q/K/V scratch
    gemm_mma<0><<<dim3(3 * DM / 128, MTOT / 128), 256, GEMM_SMEM>>>(
        xh, xl, wqh, wql, b_qkv, nullptr);

    // flash attention (HMMA + FMA-poly softmax) -> bf16 hi/lo att
    attn_mma<<<dim3(TT / 128, BH), 256, ATT_SMEM>>>(mask);

    // out projection (HMMA)
    gemm_mma<1><<<dim3(DM / 128, MTOT / 128), 256, GEMM_SMEM>>>(
        ath, atl, woh, wol, b_out, out);
}

// round 12
// speedup vs baseline: 2.6891x; 1.0564x over previous
#include <cuda_runtime.h>
#include <cuda_bf16.h>
#include <cstdint>

#define DM   768
#define NH   12
#define DH   64
#define BB   2
#define TT   4096
#define BH   (BB*NH)
#define MTOT (BB*TT)        // 8192

typedef unsigned long long u64;

// Q pre-scale: 1/sqrt(64) * log2(e)  -> logits accumulate in log2 units
#define QSCALE 0.1803368801111204f

// ---------------- scratch (__device__ globals; no cudaMalloc allowed) ------
__device__ __align__(256) __nv_bfloat16 g_Qh[(size_t)BH*TT*DH];
__device__ __align__(256) __nv_bfloat16 g_Ql[(size_t)BH*TT*DH];
__device__ __align__(256) __nv_bfloat16 g_Kh[(size_t)BH*TT*DH];
__device__ __align__(256) __nv_bfloat16 g_Kl[(size_t)BH*TT*DH];
__device__ __align__(256) __nv_bfloat16 g_Vh[(size_t)BH*TT*DH];
__device__ __align__(256) __nv_bfloat16 g_Vl[(size_t)BH*TT*DH];

__device__ __align__(256) __nv_bfloat16 g_xh[(size_t)MTOT*DM];
__device__ __align__(256) __nv_bfloat16 g_xl[(size_t)MTOT*DM];
__device__ __align__(256) __nv_bfloat16 g_wqh[(size_t)3*DM*DM];
__device__ __align__(256) __nv_bfloat16 g_wql[(size_t)3*DM*DM];
__device__ __align__(256) __nv_bfloat16 g_woh[(size_t)DM*DM];
__device__ __align__(256) __nv_bfloat16 g_wol[(size_t)DM*DM];
__device__ __align__(256) __nv_bfloat16 g_ath[(size_t)MTOT*DM];
__device__ __align__(256) __nv_bfloat16 g_atl[(size_t)MTOT*DM];

// ---------------- PTX helpers (sm_80-era: legal on plain sm_103) -----------
__device__ __forceinline__ uint32_t smem_u32(const void* p) {
    uint32_t a;
    asm("{ .reg .u64 t; cvta.to.shared.u64 t, %1; cvt.u32.u64 %0, t; }"
        : "=r"(a) : "l"(p));
    return a;
}
__device__ __forceinline__ void ldmx4(uint32_t* r, uint32_t addr) {
    asm volatile("ldmatrix.sync.aligned.m8n8.x4.shared.b16 {%0,%1,%2,%3}, [%4];"
                 : "=r"(r[0]), "=r"(r[1]), "=r"(r[2]), "=r"(r[3]) : "r"(addr));
}
__device__ __forceinline__ void ldmx4t(uint32_t* r, uint32_t addr) {
    asm volatile("ldmatrix.sync.aligned.m8n8.x4.trans.shared.b16 {%0,%1,%2,%3}, [%4];"
                 : "=r"(r[0]), "=r"(r[1]), "=r"(r[2]), "=r"(r[3]) : "r"(addr));
}
__device__ __forceinline__ void mma16816(float* c, const uint32_t* a,
                                         const uint32_t* b) {
    asm volatile(
        "mma.sync.aligned.m16n8k16.row.col.f32.bf16.bf16.f32 "
        "{%0,%1,%2,%3}, {%4,%5,%6,%7}, {%8,%9}, {%0,%1,%2,%3};"
        : "+f"(c[0]), "+f"(c[1]), "+f"(c[2]), "+f"(c[3])
        : "r"(a[0]), "r"(a[1]), "r"(a[2]), "r"(a[3]), "r"(b[0]), "r"(b[1]));
}
#define CP16(saddr, gptr) \
    asm volatile("cp.async.cg.shared.global [%0], [%1], 16;" \
                 :: "r"(saddr), "l"(gptr))
#define CPCOMMIT() asm volatile("cp.async.commit_group;" ::: "memory")
#define CPWAIT(n)  asm volatile("cp.async.wait_group %0;" :: "n"(n) : "memory")

// ---- packed f32x2 helpers ----
__device__ __forceinline__ u64 pack2(float lo, float hi) {
    u64 r; asm("mov.b64 %0,{%1,%2};" : "=l"(r) : "f"(lo), "f"(hi)); return r;
}
__device__ __forceinline__ void unpack2(u64 v, float& lo, float& hi) {
    asm("mov.b64 {%0,%1},%2;" : "=f"(lo), "=f"(hi) : "l"(v));
}
__device__ __forceinline__ u64 add2(u64 a, u64 b) {
    u64 d; asm("add.rn.f32x2 %0,%1,%2;" : "=l"(d) : "l"(a), "l"(b)); return d;
}
__device__ __forceinline__ u64 fma2v(u64 a, u64 b, u64 c) {
    u64 d; asm("fma.rn.f32x2 %0,%1,%2,%3;" : "=l"(d) : "l"(a), "l"(b), "l"(c));
    return d;
}

// MUFU-free packed exp2: magic round + degree-6 poly of 2^f, f in [-0.5,0.5].
// Inputs MUST be <= 0 (softmax-shifted). rel err ~2e-7.
__device__ __forceinline__ float2 fexp2x2(float a, float b) {
    a = fmaxf(a, -120.0f);
    b = fmaxf(b, -120.0f);
    const u64 C2   = pack2(12582912.0f, 12582912.0f);   // 1.5*2^23
    const u64 nC2  = pack2(-12582912.0f, -12582912.0f);
    const u64 m1   = pack2(-1.0f, -1.0f);
    u64 y = pack2(a, b);
    u64 t = add2(y, C2);
    float t0, t1; unpack2(t, t0, t1);
    int n0 = __float_as_int(t0) - 0x4B400000;
    int n1 = __float_as_int(t1) - 0x4B400000;
    u64 t2 = add2(t, nC2);
    u64 f  = fma2v(t2, m1, y);                          // f = y - round(y)
    u64 p  = pack2(1.5403530e-4f, 1.5403530e-4f);
    p = fma2v(p, f, pack2(1.3333558e-3f, 1.3333558e-3f));
    p = fma2v(p, f, pack2(9.6181291e-3f, 9.6181291e-3f));
    p = fma2v(p, f, pack2(5.5504109e-2f, 5.5504109e-2f));
    p = fma2v(p, f, pack2(2.4022651e-1f, 2.4022651e-1f));
    p = fma2v(p, f, pack2(6.9314718e-1f, 6.9314718e-1f));
    p = fma2v(p, f, pack2(1.0f, 1.0f));
    float p0, p1; unpack2(p, p0, p1);
    float2 r;
    r.x = __int_as_float(__float_as_int(p0) + (n0 << 23));
    r.y = __int_as_float(__float_as_int(p1) + (n1 << 23));
    return r;
}
__device__ __forceinline__ float fexp2s(float a) {
    float2 r = fexp2x2(a, a);
    return r.x;
}

// ---------------- fp32 -> bf16 hi/lo split ----------------------------------
__global__ __launch_bounds__(256) void split_kernel(const float* __restrict__ in,
                                                    __nv_bfloat162* __restrict__ hi,
                                                    __nv_bfloat162* __restrict__ lo,
                                                    int n2) {
    int i = blockIdx.x * 256 + threadIdx.x;
    if (i < n2) {
        float2 v = ((const float2*)in)[i];
        __nv_bfloat16 hx = __float2bfloat16(v.x);
        __nv_bfloat16 hy = __float2bfloat16(v.y);
        float rx = v.x - __bfloat162float(hx);
        float ry = v.y - __bfloat162float(hy);
        hi[i] = __halves2bfloat162(hx, hy);
        lo[i] = __halves2bfloat162(__float2bfloat16(rx), __float2bfloat16(ry));
    }
}

// ---------------- HMMA GEMM: C = A @ B^T (+bias) ----------------------------
// MODE 0: qkv -> scatter bf16 hi/lo into g_Q*/g_K*/g_V* (Q scaled by QSCALE).
// MODE 1: out -> fp32 dst[m*768+n].
#define KT       32
#define SSTRIDE  40
#define TILE_B   (128 * SSTRIDE * 2)
#define STAGE_B  (4 * TILE_B)
#define GEMM_SMEM (2 * STAGE_B)

template <int MODE>
__global__ __launch_bounds__(256, 2) void gemm_mma(const __nv_bfloat16* __restrict__ Ah,
                                                   const __nv_bfloat16* __restrict__ Al,
                                                   const __nv_bfloat16* __restrict__ Bh,
                                                   const __nv_bfloat16* __restrict__ Bl,
                                                   const float* __restrict__ bias,
                                                   float* __restrict__ dst) {
    extern __shared__ char smem[];
    const uint32_t sb = smem_u32(smem);
    const int tid = threadIdx.x, wid = tid >> 5, lane = tid & 31;
    const int n0 = blockIdx.x * 128, m0 = blockIdx.y * 128;
    const int wm = wid & 1, wn = wid >> 1;

    const int r_ld[2]  = { (tid + 0)   >> 2, (tid + 256) >> 2 };
    const int c8_ld[2] = { (tid + 0) & 3,    (tid + 256) & 3 };

    auto issue = [&](int kt, int stage) {
        const int k0 = kt * KT;
        const uint32_t s0 = sb + stage * STAGE_B;
#pragma unroll
        for (int h = 0; h < 2; h++) {
            const int r = r_ld[h], c8 = c8_ld[h];
            const uint32_t so = (uint32_t)(r * (SSTRIDE * 2) + c8 * 16);
            const size_t ga = (size_t)(m0 + r) * DM + k0 + c8 * 8;
            const size_t gb = (size_t)(n0 + r) * DM + k0 + c8 * 8;
            CP16(s0 + 0 * TILE_B + so, Ah + ga);
            CP16(s0 + 1 * TILE_B + so, Al + ga);
            CP16(s0 + 2 * TILE_B + so, Bh + gb);
            CP16(s0 + 3 * TILE_B + so, Bl + gb);
        }
    };

    float C[4][4][4] = {};

    issue(0, 0);
    CPCOMMIT();
    int stage = 0;
    const int NKT = DM / KT;
    for (int kt = 0; kt < NKT; kt++) {
        if (kt + 1 < NKT) { issue(kt + 1, stage ^ 1); CPCOMMIT(); CPWAIT(1); }
        else              { CPWAIT(0); }
        __syncthreads();

        const uint32_t s0 = sb + stage * STAGE_B;
        const uint32_t aRow = (uint32_t)(wm * 64 + (lane & 15));
        const uint32_t aK   = (uint32_t)((lane >> 4) * 8);
        const uint32_t bRow = (uint32_t)(wn * 32 + (lane & 7) + ((lane >> 4) & 1) * 8);
        const uint32_t bK   = (uint32_t)(((lane >> 3) & 1) * 8);
#pragma unroll
        for (int s = 0; s < 2; s++) {
            uint32_t ah[4][4], al[4][4], bh[2][4], bl[2][4];
#pragma unroll
            for (int mt = 0; mt < 4; mt++) {
                uint32_t off = (aRow + mt * 16) * (SSTRIDE * 2) + (aK + s * 16) * 2;
                ldmx4(ah[mt], s0 + 0 * TILE_B + off);
                ldmx4(al[mt], s0 + 1 * TILE_B + off);
            }
#pragma unroll
            for (int nt = 0; nt < 2; nt++) {
                uint32_t off = (bRow + nt * 16) * (SSTRIDE * 2) + (bK + s * 16) * 2;
                ldmx4(bh[nt], s0 + 2 * TILE_B + off);
                ldmx4(bl[nt], s0 + 3 * TILE_B + off);
            }
#pragma unroll
            for (int mt = 0; mt < 4; mt++) {
#pragma unroll
                for (int nt = 0; nt < 2; nt++) {
#pragma unroll
                    for (int ns = 0; ns < 2; ns++) {
                        float* c = C[mt][nt * 2 + ns];
                        mma16816(c, ah[mt], &bh[nt][ns * 2]);
                        mma16816(c, ah[mt], &bl[nt][ns * 2]);
                        mma16816(c, al[mt], &bh[nt][ns * 2]);
                    }
                }
            }
        }
        __syncthreads();
        stage ^= 1;
    }

    const int g = lane >> 2, tg = lane & 3;
#pragma unroll
    for (int mt = 0; mt < 4; mt++) {
#pragma unroll
        for (int n8 = 0; n8 < 4; n8++) {
            const int col = n0 + wn * 32 + n8 * 8 + 2 * tg;
            const int row = m0 + wm * 64 + mt * 16 + g;
            const float b0 = bias[col], b1 = bias[col + 1];
            float* c = C[mt][n8];
            if (MODE == 0) {
                const int which = col / DM;
                const int hd = (col % DM) >> 6;
                const int d0 = col & 63;
                __nv_bfloat16 *dph, *dpl;
                if (which == 0)      { dph = g_Qh; dpl = g_Ql; }
                else if (which == 1) { dph = g_Kh; dpl = g_Kl; }
                else                 { dph = g_Vh; dpl = g_Vl; }
                const float sc = (which == 0) ? QSCALE : 1.0f;
#pragma unroll
                for (int hrow = 0; hrow < 2; hrow++) {
                    const int m = row + hrow * 8;
                    const int bb = m >> 12, t = m & 4095;
                    const size_t idx = (((size_t)(bb * NH + hd)) * TT + t) * DH + d0;
                    float v0 = (c[2 * hrow + 0] + b0) * sc;
                    float v1 = (c[2 * hrow + 1] + b1) * sc;
                    __nv_bfloat162 h2 = __floats2bfloat162_rn(v0, v1);
                    float2 hf = __bfloat1622float2(h2);
                    __nv_bfloat162 l2 = __floats2bfloat162_rn(v0 - hf.x, v1 - hf.y);
                    *(__nv_bfloat162*)(dph + idx) = h2;
                    *(__nv_bfloat162*)(dpl + idx) = l2;
                }
            } else {
#pragma unroll
                for (int hrow = 0; hrow < 2; hrow++) {
                    const int m = row + hrow * 8;
                    float2 v;
                    v.x = c[2 * hrow + 0] + b0;
                    v.y = c[2 * hrow + 1] + b1;
                    *(float2*)(dst + (size_t)m * DM + col) = v;
                }
            }
        }
    }
}

// ---------------- HMMA flash attention --------------------------------------
// CTA = 128 q-rows x one (b,h); 8 warps, each owns 16 q-rows (full k width).
// Logits in log2 units (QSCALE includes log2e) -> softmax uses exp2 directly.
#define AST      72                       // bf16 stride (144 B rows)
#define ATILE_B  (128 * AST * 2)          // 18432 B per tensor tile
#define ASTAGE_B (4 * ATILE_B)            // K/V hi/lo = 73728 B
#define AMASK_OFF (2 * ASTAGE_B)          // 147456
#define ATT_SMEM  (AMASK_OFF + TT * 4)    // +16 KB mask floats = 163840

__global__ __launch_bounds__(256) void attn_mma(const int* __restrict__ mask) {
    extern __shared__ char smraw[];
    const uint32_t sb = smem_u32(smraw);
    float* mskf = (float*)(smraw + AMASK_OFF);

    const int tid = threadIdx.x, w = tid >> 5, lane = tid & 31;
    const int bh = blockIdx.y, b = bh / NH, head = bh % NH;
    const int q0 = blockIdx.x * 128;
    const size_t kvbase = (size_t)bh * TT * DH;

    // mask -> additive floats (log2 units; -1e9 is still -inf-ish)
    for (int i = tid; i < TT / 4; i += 256) {
        int4 mm = ((const int4*)(mask + (size_t)b * TT))[i];
        float4 f;
        f.x = mm.x ? 0.f : -1e9f; f.y = mm.y ? 0.f : -1e9f;
        f.z = mm.z ? 0.f : -1e9f; f.w = mm.w ? 0.f : -1e9f;
        ((float4*)mskf)[i] = f;
    }

    // stage Q (hi/lo) into stage-0 K buffers, extract fragments to registers
    {
        const size_t qb = kvbase + (size_t)q0 * DH;
#pragma unroll
        for (int h = 0; h < 4; h++) {
            int c = tid + h * 256;
            int r = c >> 3, k8 = c & 7;
            uint32_t so = r * 144 + k8 * 16;
            CP16(sb + so,           g_Qh + qb + r * 64 + k8 * 8);
            CP16(sb + ATILE_B + so, g_Ql + qb + r * 64 + k8 * 8);
        }
        CPCOMMIT(); CPWAIT(0);
    }
    __syncthreads();
    uint32_t aQh[4][4], aQl[4][4];
    {
        uint32_t row = 16 * w + (lane & 15);
#pragma unroll
        for (int ks = 0; ks < 4; ks++) {
            uint32_t off = row * 144 + (2 * ks + (lane >> 4)) * 16;
            ldmx4(aQh[ks], sb + off);
            ldmx4(aQl[ks], sb + ATILE_B + off);
        }
    }
    __syncthreads();

    auto issue = [&](int jt, int s) {
        const size_t gbase = kvbase + (size_t)jt * 128 * DH;
        const uint32_t s0 = sb + s * ASTAGE_B;
#pragma unroll
        for (int h = 0; h < 4; h++) {
            int c = tid + h * 256;
            int r = c >> 3, k8 = c & 7;
            uint32_t so = r * 144 + k8 * 16;
            size_t gg = gbase + r * 64 + k8 * 8;
            CP16(s0 + 0 * ATILE_B + so, g_Kh + gg);
            CP16(s0 + 1 * ATILE_B + so, g_Kl + gg);
            CP16(s0 + 2 * ATILE_B + so, g_Vh + gg);
            CP16(s0 + 3 * ATILE_B + so, g_Vl + gg);
        }
    };

    issue(0, 0); CPCOMMIT();

    float O[8][4] = {};
    float mr0 = -1e30f, mr1 = -1e30f, lw0 = 0.f, lw1 = 0.f;
    int stage = 0;

    const uint32_t bRow = (lane & 7) + ((lane >> 4) << 3);       // K frag rows
    const uint32_t bCs  = (lane >> 3) & 1;                       // K chunk sel
    const uint32_t vRow = (lane & 7) + (((lane >> 3) & 1) << 3); // V frag rows
    const uint32_t vCs  = lane >> 4;                             // V chunk sel

    for (int jt = 0; jt < TT / 128; jt++) {
        if (jt + 1 < TT / 128) { issue(jt + 1, stage ^ 1); CPCOMMIT(); CPWAIT(1); }
        else                   { CPWAIT(0); }
        __syncthreads();
        const uint32_t s0 = sb + stage * ASTAGE_B;
        const uint32_t sKh = s0, sKl = s0 + ATILE_B;
        const uint32_t sVh = s0 + 2 * ATILE_B, sVl = s0 + 3 * ATILE_B;

        // ---- S = Q @ K^T (3-term split), log2 units ----
        float Cs[16][4] = {};
#pragma unroll
        for (int ks = 0; ks < 4; ks++) {
#pragma unroll
            for (int nt = 0; nt < 8; nt++) {
                uint32_t off = (16 * nt + bRow) * 144 + (2 * ks + bCs) * 16;
                uint32_t kh4[4], kl4[4];
                ldmx4(kh4, sKh + off);
                ldmx4(kl4, sKl + off);
                mma16816(Cs[2 * nt],     aQh[ks], &kh4[0]);
                mma16816(Cs[2 * nt],     aQh[ks], &kl4[0]);
                mma16816(Cs[2 * nt],     aQl[ks], &kh4[0]);
                mma16816(Cs[2 * nt + 1], aQh[ks], &kh4[2]);
                mma16816(Cs[2 * nt + 1], aQh[ks], &kl4[2]);
                mma16816(Cs[2 * nt + 1], aQl[ks], &kh4[2]);
            }
        }

        // ---- mask + online softmax (base 2) ----
        float mx0 = -1e30f, mx1 = -1e30f;
#pragma unroll
        for (int t = 0; t < 16; t++) {
            float2 mk = *(const float2*)&mskf[jt * 128 + 8 * t + 2 * (lane & 3)];
            Cs[t][0] += mk.x; Cs[t][1] += mk.y;
            Cs[t][2] += mk.x; Cs[t][3] += mk.y;
            mx0 = fmaxf(mx0, fmaxf(Cs[t][0], Cs[t][1]));
            mx1 = fmaxf(mx1, fmaxf(Cs[t][2], Cs[t][3]));
        }
        mx0 = fmaxf(mx0, __shfl_xor_sync(0xffffffffu, mx0, 1));
        mx0 = fmaxf(mx0, __shfl_xor_sync(0xffffffffu, mx0, 2));
        mx1 = fmaxf(mx1, __shfl_xor_sync(0xffffffffu, mx1, 1));
        mx1 = fmaxf(mx1, __shfl_xor_sync(0xffffffffu, mx1, 2));
        float mn0 = fmaxf(mr0, mx0), mn1 = fmaxf(mr1, mx1);
        float2 alp = fexp2x2(mr0 - mn0, mr1 - mn1);
        float al0 = alp.x, al1 = alp.y;

        uint32_t ph0[16], ph1[16], pl0[16], pl1[16];
        float sum0 = 0.f, sum1 = 0.f;
#pragma unroll
        for (int t = 0; t < 16; t++) {
            float2 p01 = fexp2x2(Cs[t][0] - mn0, Cs[t][1] - mn0);
            float2 p23 = fexp2x2(Cs[t][2] - mn1, Cs[t][3] - mn1);
            sum0 += p01.x + p01.y; sum1 += p23.x + p23.y;
            __nv_bfloat162 h01 = __floats2bfloat162_rn(p01.x, p01.y);
            __nv_bfloat162 h23 = __floats2bfloat162_rn(p23.x, p23.y);
            float2 f01 = __bfloat1622float2(h01);
            float2 f23 = __bfloat1622float2(h23);
            __nv_bfloat162 l01 = __floats2bfloat162_rn(p01.x - f01.x, p01.y - f01.y);
            __nv_bfloat162 l23 = __floats2bfloat162_rn(p23.x - f23.x, p23.y - f23.y);
            ph0[t] = *(uint32_t*)&h01; ph1[t] = *(uint32_t*)&h23;
            pl0[t] = *(uint32_t*)&l01; pl1[t] = *(uint32_t*)&l23;
        }
        sum0 += __shfl_xor_sync(0xffffffffu, sum0, 1);
        sum0 += __shfl_xor_sync(0xffffffffu, sum0, 2);
        sum1 += __shfl_xor_sync(0xffffffffu, sum1, 1);
        sum1 += __shfl_xor_sync(0xffffffffu, sum1, 2);
        lw0 = lw0 * al0 + sum0;  lw1 = lw1 * al1 + sum1;
        mr0 = mn0;  mr1 = mn1;

        // ---- O = O*alpha + P @ V (3-term split) ----
#pragma unroll
        for (int dt = 0; dt < 8; dt++) {
            O[dt][0] *= al0; O[dt][1] *= al0;
            O[dt][2] *= al1; O[dt][3] *= al1;
        }
#pragma unroll
        for (int j = 0; j < 8; j++) {
            uint32_t Ahh[4] = { ph0[2 * j], ph1[2 * j], ph0[2 * j + 1], ph1[2 * j + 1] };
            uint32_t All[4] = { pl0[2 * j], pl1[2 * j], pl0[2 * j + 1], pl1[2 * j + 1] };
#pragma unroll
            for (int dp = 0; dp < 4; dp++) {
                uint32_t off = (16 * j + vRow) * 144 + (2 * dp + vCs) * 16;
                uint32_t vh4[4], vl4[4];
                ldmx4t(vh4, sVh + off);
                ldmx4t(vl4, sVl + off);
                mma16816(O[2 * dp],     Ahh, &vh4[0]);
                mma16816(O[2 * dp],     Ahh, &vl4[0]);
                mma16816(O[2 * dp],     All, &vh4[0]);
                mma16816(O[2 * dp + 1], Ahh, &vh4[2]);
                mma16816(O[2 * dp + 1], Ahh, &vl4[2]);
                mma16816(O[2 * dp + 1], All, &vh4[2]);
            }
        }
        __syncthreads();
        stage ^= 1;
    }

    // ---- epilogue: normalize, write bf16 hi/lo att in [B,T,H*Dh] ----------
    float inv0 = 1.0f / lw0, inv1 = 1.0f / lw1;
    const int t_lo = q0 + 16 * w + (lane >> 2);
    const size_t m_lo = (size_t)b * TT + t_lo;
#pragma unroll
    for (int dt = 0; dt < 8; dt++) {
        const int col = head * 64 + 8 * dt + 2 * (lane & 3);
#pragma unroll
        for (int hrow = 0; hrow < 2; hrow++) {
            const size_t idx = (m_lo + hrow * 8) * DM + col;
            float v0 = O[dt][2 * hrow + 0] * (hrow ? inv1 : inv0);
            float v1 = O[dt][2 * hrow + 1] * (hrow ? inv1 : inv0);
            __nv_bfloat162 h2 = __floats2bfloat162_rn(v0, v1);
            float2 hf = __bfloat1622float2(h2);
            __nv_bfloat162 l2 = __floats2bfloat162_rn(v0 - hf.x, v1 - hf.y);
            *(__nv_bfloat162*)(g_ath + idx) = h2;
            *(__nv_bfloat162*)(g_atl + idx) = l2;
        }
    }
}

// ---------------------------------------------------------------------------
// Inputs (metadata order): x, w_qkv, b_qkv, w_out, b_out, mask. Output: float32.
// ---------------------------------------------------------------------------
extern "C" void kernel_launch(void* const* d_in, const int* in_sizes, int n_in,
                              void* d_out, int out_size) {
    const float* x     = (const float*)d_in[0];
    const float* w_qkv = (const float*)d_in[1];
    const float* b_qkv = (const float*)d_in[2];
    const float* w_out = (const float*)d_in[3];
    const float* b_out = (const float*)d_in[4];
    const int*   mask  = (const int*)d_in[5];
    float* out = (float*)d_out;

    cudaFuncSetAttribute(gemm_mma<0>, cudaFuncAttributeMaxDynamicSharedMemorySize,
                         GEMM_SMEM);
    cudaFuncSetAttribute(gemm_mma<1>, cudaFuncAttributeMaxDynamicSharedMemorySize,
                         GEMM_SMEM);
    cudaFuncSetAttribute(attn_mma, cudaFuncAttributeMaxDynamicSharedMemorySize,
                         ATT_SMEM);

    __nv_bfloat16 *xh, *xl, *wqh, *wql, *woh, *wol, *ath, *atl;
    cudaGetSymbolAddress((void**)&xh,  g_xh);
    cudaGetSymbolAddress((void**)&xl,  g_xl);
    cudaGetSymbolAddress((void**)&wqh, g_wqh);
    cudaGetSymbolAddress((void**)&wql, g_wql);
    cudaGetSymbolAddress((void**)&woh, g_woh);
    cudaGetSymbolAddress((void**)&wol, g_wol);
    cudaGetSymbolAddress((void**)&ath, g_ath);
    cudaGetSymbolAddress((void**)&atl, g_atl);

    int nx = MTOT * DM / 2, nq = 3 * DM * DM / 2, no = DM * DM / 2;
    split_kernel<<<(nx + 255) / 256, 256>>>(x, (__nv_bfloat162*)xh,
                                            (__nv_bfloat162*)xl, nx);
    split_kernel<<<(nq + 255) / 256, 256>>>(w_qkv, (__nv_bfloat162*)wqh,
                                            (__nv_bfloat162*)wql, nq);
    split_kernel<<<(no + 255) / 256, 256>>>(w_out, (__nv_bfloat162*)woh,
                                            (__nv_bfloat162*)wol, no);

    // QKV projection (HMMA) -> bf16 hi/lo Q/K/V scratch
    gemm_mma<0><<<dim3(3 * DM / 128, MTOT / 128), 256, GEMM_SMEM>>>(
        xh, xl, wqh, wql, b_qkv, nullptr);

    // flash attention (HMMA + packed exp2 softmax) -> bf16 hi/lo att
    attn_mma<<<dim3(TT / 128, BH), 256, ATT_SMEM>>>(mask);

    // out projection (HMMA)
    gemm_mma<1><<<dim3(DM / 128, MTOT / 128), 256, GEMM_SMEM>>>(
        ath, atl, woh, wol, b_out, out);
}

// round 13
// speedup vs baseline: 2.8421x; 1.0569x over previous
#include <cuda_runtime.h>
#include <cuda_bf16.h>
#include <cstdint>

#define DM   768
#define NH   12
#define DH   64
#define BB   2
#define TT   4096
#define BH   (BB*NH)
#define MTOT (BB*TT)        // 8192

typedef unsigned long long u64;

// Q pre-scale: 1/sqrt(64) * log2(e)  -> logits accumulate in log2 units
#define QSCALE 0.1803368801111204f

// ---------------- scratch (__device__ globals; no cudaMalloc allowed) ------
__device__ __align__(256) __nv_bfloat16 g_Qh[(size_t)BH*TT*DH];
__device__ __align__(256) __nv_bfloat16 g_Ql[(size_t)BH*TT*DH];
__device__ __align__(256) __nv_bfloat16 g_Kh[(size_t)BH*TT*DH];
__device__ __align__(256) __nv_bfloat16 g_Kl[(size_t)BH*TT*DH];
__device__ __align__(256) __nv_bfloat16 g_Vh[(size_t)BH*TT*DH];
__device__ __align__(256) __nv_bfloat16 g_Vl[(size_t)BH*TT*DH];

__device__ __align__(256) __nv_bfloat16 g_xh[(size_t)MTOT*DM];
__device__ __align__(256) __nv_bfloat16 g_xl[(size_t)MTOT*DM];
__device__ __align__(256) __nv_bfloat16 g_wqh[(size_t)3*DM*DM];
__device__ __align__(256) __nv_bfloat16 g_wql[(size_t)3*DM*DM];
__device__ __align__(256) __nv_bfloat16 g_woh[(size_t)DM*DM];
__device__ __align__(256) __nv_bfloat16 g_wol[(size_t)DM*DM];
__device__ __align__(256) __nv_bfloat16 g_ath[(size_t)MTOT*DM];
__device__ __align__(256) __nv_bfloat16 g_atl[(size_t)MTOT*DM];

// ---------------- PTX helpers (sm_80-era: legal on plain sm_103) -----------
__device__ __forceinline__ uint32_t smem_u32(const void* p) {
    uint32_t a;
    asm("{ .reg .u64 t; cvta.to.shared.u64 t, %1; cvt.u32.u64 %0, t; }"
        : "=r"(a) : "l"(p));
    return a;
}
__device__ __forceinline__ void ldmx4(uint32_t* r, uint32_t addr) {
    asm volatile("ldmatrix.sync.aligned.m8n8.x4.shared.b16 {%0,%1,%2,%3}, [%4];"
                 : "=r"(r[0]), "=r"(r[1]), "=r"(r[2]), "=r"(r[3]) : "r"(addr));
}
__device__ __forceinline__ void ldmx4t(uint32_t* r, uint32_t addr) {
    asm volatile("ldmatrix.sync.aligned.m8n8.x4.trans.shared.b16 {%0,%1,%2,%3}, [%4];"
                 : "=r"(r[0]), "=r"(r[1]), "=r"(r[2]), "=r"(r[3]) : "r"(addr));
}
__device__ __forceinline__ void mma16816(float* c, const uint32_t* a,
                                         const uint32_t* b) {
    asm volatile(
        "mma.sync.aligned.m16n8k16.row.col.f32.bf16.bf16.f32 "
        "{%0,%1,%2,%3}, {%4,%5,%6,%7}, {%8,%9}, {%0,%1,%2,%3};"
        : "+f"(c[0]), "+f"(c[1]), "+f"(c[2]), "+f"(c[3])
        : "r"(a[0]), "r"(a[1]), "r"(a[2]), "r"(a[3]), "r"(b[0]), "r"(b[1]));
}
#define CP16(saddr, gptr) \
    asm volatile("cp.async.cg.shared.global [%0], [%1], 16;" \
                 :: "r"(saddr), "l"(gptr))
#define CPCOMMIT() asm volatile("cp.async.commit_group;" ::: "memory")
#define CPWAIT(n)  asm volatile("cp.async.wait_group %0;" :: "n"(n) : "memory")

// ---- packed f32x2 helpers ----
__device__ __forceinline__ u64 pack2(float lo, float hi) {
    u64 r; asm("mov.b64 %0,{%1,%2};" : "=l"(r) : "f"(lo), "f"(hi)); return r;
}
__device__ __forceinline__ void unpack2(u64 v, float& lo, float& hi) {
    asm("mov.b64 {%0,%1},%2;" : "=f"(lo), "=f"(hi) : "l"(v));
}
__device__ __forceinline__ u64 add2(u64 a, u64 b) {
    u64 d; asm("add.rn.f32x2 %0,%1,%2;" : "=l"(d) : "l"(a), "l"(b)); return d;
}
__device__ __forceinline__ u64 fma2v(u64 a, u64 b, u64 c) {
    u64 d; asm("fma.rn.f32x2 %0,%1,%2,%3;" : "=l"(d) : "l"(a), "l"(b), "l"(c));
    return d;
}

// MUFU-free packed exp2: magic round + degree-6 poly of 2^f, f in [-0.5,0.5].
// Inputs MUST be <= 0 (softmax-shifted). rel err ~2e-7.
__device__ __forceinline__ float2 fexp2x2(float a, float b) {
    a = fmaxf(a, -120.0f);
    b = fmaxf(b, -120.0f);
    const u64 C2   = pack2(12582912.0f, 12582912.0f);   // 1.5*2^23
    const u64 nC2  = pack2(-12582912.0f, -12582912.0f);
    const u64 m1   = pack2(-1.0f, -1.0f);
    u64 y = pack2(a, b);
    u64 t = add2(y, C2);
    float t0, t1; unpack2(t, t0, t1);
    int n0 = __float_as_int(t0) - 0x4B400000;
    int n1 = __float_as_int(t1) - 0x4B400000;
    u64 t2 = add2(t, nC2);
    u64 f  = fma2v(t2, m1, y);                          // f = y - round(y)
    u64 p  = pack2(1.5403530e-4f, 1.5403530e-4f);
    p = fma2v(p, f, pack2(1.3333558e-3f, 1.3333558e-3f));
    p = fma2v(p, f, pack2(9.6181291e-3f, 9.6181291e-3f));
    p = fma2v(p, f, pack2(5.5504109e-2f, 5.5504109e-2f));
    p = fma2v(p, f, pack2(2.4022651e-1f, 2.4022651e-1f));
    p = fma2v(p, f, pack2(6.9314718e-1f, 6.9314718e-1f));
    p = fma2v(p, f, pack2(1.0f, 1.0f));
    float p0, p1; unpack2(p, p0, p1);
    float2 r;
    r.x = __int_as_float(__float_as_int(p0) + (n0 << 23));
    r.y = __int_as_float(__float_as_int(p1) + (n1 << 23));
    return r;
}

// ---------------- fp32 -> bf16 hi/lo split ----------------------------------
__global__ __launch_bounds__(256) void split_kernel(const float* __restrict__ in,
                                                    __nv_bfloat162* __restrict__ hi,
                                                    __nv_bfloat162* __restrict__ lo,
                                                    int n2) {
    int i = blockIdx.x * 256 + threadIdx.x;
    if (i < n2) {
        float2 v = ((const float2*)in)[i];
        __nv_bfloat16 hx = __float2bfloat16(v.x);
        __nv_bfloat16 hy = __float2bfloat16(v.y);
        float rx = v.x - __bfloat162float(hx);
        float ry = v.y - __bfloat162float(hy);
        hi[i] = __halves2bfloat162(hx, hy);
        lo[i] = __halves2bfloat162(__float2bfloat16(rx), __float2bfloat16(ry));
    }
}

// ---------------- HMMA GEMM: C = A @ B^T (+bias) ----------------------------
// MODE 0: qkv -> scatter bf16 hi/lo into g_Q*/g_K*/g_V* (Q scaled by QSCALE).
// MODE 1: out -> fp32 dst[m*768+n].
#define KT       32
#define SSTRIDE  40
#define TILE_B   (128 * SSTRIDE * 2)
#define STAGE_B  (4 * TILE_B)
#define GEMM_SMEM (2 * STAGE_B)

template <int MODE>
__global__ __launch_bounds__(256, 2) void gemm_mma(const __nv_bfloat16* __restrict__ Ah,
                                                   const __nv_bfloat16* __restrict__ Al,
                                                   const __nv_bfloat16* __restrict__ Bh,
                                                   const __nv_bfloat16* __restrict__ Bl,
                                                   const float* __restrict__ bias,
                                                   float* __restrict__ dst) {
    extern __shared__ char smem[];
    const uint32_t sb = smem_u32(smem);
    const int tid = threadIdx.x, wid = tid >> 5, lane = tid & 31;
    const int n0 = blockIdx.x * 128, m0 = blockIdx.y * 128;
    const int wm = wid & 1, wn = wid >> 1;

    const int r_ld[2]  = { (tid + 0)   >> 2, (tid + 256) >> 2 };
    const int c8_ld[2] = { (tid + 0) & 3,    (tid + 256) & 3 };

    auto issue = [&](int kt, int stage) {
        const int k0 = kt * KT;
        const uint32_t s0 = sb + stage * STAGE_B;
#pragma unroll
        for (int h = 0; h < 2; h++) {
            const int r = r_ld[h], c8 = c8_ld[h];
            const uint32_t so = (uint32_t)(r * (SSTRIDE * 2) + c8 * 16);
            const size_t ga = (size_t)(m0 + r) * DM + k0 + c8 * 8;
            const size_t gb = (size_t)(n0 + r) * DM + k0 + c8 * 8;
            CP16(s0 + 0 * TILE_B + so, Ah + ga);
            CP16(s0 + 1 * TILE_B + so, Al + ga);
            CP16(s0 + 2 * TILE_B + so, Bh + gb);
            CP16(s0 + 3 * TILE_B + so, Bl + gb);
        }
    };

    float C[4][4][4] = {};

    issue(0, 0);
    CPCOMMIT();
    int stage = 0;
    const int NKT = DM / KT;
    for (int kt = 0; kt < NKT; kt++) {
        if (kt + 1 < NKT) { issue(kt + 1, stage ^ 1); CPCOMMIT(); CPWAIT(1); }
        else              { CPWAIT(0); }
        __syncthreads();

        const uint32_t s0 = sb + stage * STAGE_B;
        const uint32_t aRow = (uint32_t)(wm * 64 + (lane & 15));
        const uint32_t aK   = (uint32_t)((lane >> 4) * 8);
        const uint32_t bRow = (uint32_t)(wn * 32 + (lane & 7) + ((lane >> 4) & 1) * 8);
        const uint32_t bK   = (uint32_t)(((lane >> 3) & 1) * 8);
#pragma unroll
        for (int s = 0; s < 2; s++) {
            uint32_t ah[4][4], al[4][4], bh[2][4], bl[2][4];
#pragma unroll
            for (int mt = 0; mt < 4; mt++) {
                uint32_t off = (aRow + mt * 16) * (SSTRIDE * 2) + (aK + s * 16) * 2;
                ldmx4(ah[mt], s0 + 0 * TILE_B + off);
                ldmx4(al[mt], s0 + 1 * TILE_B + off);
            }
#pragma unroll
            for (int nt = 0; nt < 2; nt++) {
                uint32_t off = (bRow + nt * 16) * (SSTRIDE * 2) + (bK + s * 16) * 2;
                ldmx4(bh[nt], s0 + 2 * TILE_B + off);
                ldmx4(bl[nt], s0 + 3 * TILE_B + off);
            }
#pragma unroll
            for (int mt = 0; mt < 4; mt++) {
#pragma unroll
                for (int nt = 0; nt < 2; nt++) {
#pragma unroll
                    for (int ns = 0; ns < 2; ns++) {
                        float* c = C[mt][nt * 2 + ns];
                        mma16816(c, ah[mt], &bh[nt][ns * 2]);
                        mma16816(c, ah[mt], &bl[nt][ns * 2]);
                        mma16816(c, al[mt], &bh[nt][ns * 2]);
                    }
                }
            }
        }
        __syncthreads();
        stage ^= 1;
    }

    const int g = lane >> 2, tg = lane & 3;
#pragma unroll
    for (int mt = 0; mt < 4; mt++) {
#pragma unroll
        for (int n8 = 0; n8 < 4; n8++) {
            const int col = n0 + wn * 32 + n8 * 8 + 2 * tg;
            const int row = m0 + wm * 64 + mt * 16 + g;
            const float b0 = bias[col], b1 = bias[col + 1];
            float* c = C[mt][n8];
            if (MODE == 0) {
                const int which = col / DM;
                const int hd = (col % DM) >> 6;
                const int d0 = col & 63;
                __nv_bfloat16 *dph, *dpl;
                if (which == 0)      { dph = g_Qh; dpl = g_Ql; }
                else if (which == 1) { dph = g_Kh; dpl = g_Kl; }
                else                 { dph = g_Vh; dpl = g_Vl; }
                const float sc = (which == 0) ? QSCALE : 1.0f;
#pragma unroll
                for (int hrow = 0; hrow < 2; hrow++) {
                    const int m = row + hrow * 8;
                    const int bb = m >> 12, t = m & 4095;
                    const size_t idx = (((size_t)(bb * NH + hd)) * TT + t) * DH + d0;
                    float v0 = (c[2 * hrow + 0] + b0) * sc;
                    float v1 = (c[2 * hrow + 1] + b1) * sc;
                    __nv_bfloat162 h2 = __floats2bfloat162_rn(v0, v1);
                    float2 hf = __bfloat1622float2(h2);
                    __nv_bfloat162 l2 = __floats2bfloat162_rn(v0 - hf.x, v1 - hf.y);
                    *(__nv_bfloat162*)(dph + idx) = h2;
                    *(__nv_bfloat162*)(dpl + idx) = l2;
                }
            } else {
#pragma unroll
                for (int hrow = 0; hrow < 2; hrow++) {
                    const int m = row + hrow * 8;
                    float2 v;
                    v.x = c[2 * hrow + 0] + b0;
                    v.y = c[2 * hrow + 1] + b1;
                    *(float2*)(dst + (size_t)m * DM + col) = v;
                }
            }
        }
    }
}

// ---------------- HMMA flash attention --------------------------------------
// CTA = 128 q-rows x one (b,h); 8 warps, each owns 16 q-rows (full k width).
// K-tile 64 (smem 88 KB -> 2 CTAs/SM). Logits in log2 units -> exp2 softmax.
#define AST      72                       // bf16 stride (144 B rows)
#define ATILE_B  (64 * AST * 2)           // 9216 B per tensor tile (64 rows)
#define ASTAGE_B (4 * ATILE_B)            // K/V hi/lo = 36864 B
#define AMASK_OFF (2 * ASTAGE_B)          // 73728
#define ATT_SMEM  (AMASK_OFF + TT * 4)    // +16 KB mask floats = 90112

__global__ __launch_bounds__(256, 2) void attn_mma(const int* __restrict__ mask) {
    extern __shared__ char smraw[];
    const uint32_t sb = smem_u32(smraw);
    float* mskf = (float*)(smraw + AMASK_OFF);

    const int tid = threadIdx.x, w = tid >> 5, lane = tid & 31;
    const int bh = blockIdx.y, b = bh / NH, head = bh % NH;
    const int q0 = blockIdx.x * 128;
    const size_t kvbase = (size_t)bh * TT * DH;

    // mask -> additive floats (log2 units; -1e9 is still -inf-ish)
    for (int i = tid; i < TT / 4; i += 256) {
        int4 mm = ((const int4*)(mask + (size_t)b * TT))[i];
        float4 f;
        f.x = mm.x ? 0.f : -1e9f; f.y = mm.y ? 0.f : -1e9f;
        f.z = mm.z ? 0.f : -1e9f; f.w = mm.w ? 0.f : -1e9f;
        ((float4*)mskf)[i] = f;
    }

    // stage Q (hi/lo: 128 rows each = 18432 B each) across stage-0 region
    {
        const size_t qb = kvbase + (size_t)q0 * DH;
#pragma unroll
        for (int h = 0; h < 4; h++) {
            int c = tid + h * 256;
            int r = c >> 3, k8 = c & 7;
            uint32_t so = r * 144 + k8 * 16;
            CP16(sb + so,                g_Qh + qb + r * 64 + k8 * 8);
            CP16(sb + 2 * ATILE_B + so,  g_Ql + qb + r * 64 + k8 * 8);
        }
        CPCOMMIT(); CPWAIT(0);
    }
    __syncthreads();
    uint32_t aQh[4][4], aQl[4][4];
    {
        uint32_t row = 16 * w + (lane & 15);
#pragma unroll
        for (int ks = 0; ks < 4; ks++) {
            uint32_t off = row * 144 + (2 * ks + (lane >> 4)) * 16;
            ldmx4(aQh[ks], sb + off);
            ldmx4(aQl[ks], sb + 2 * ATILE_B + off);
        }
    }
    __syncthreads();

    auto issue = [&](int jt, int s) {
        const size_t gbase = kvbase + (size_t)jt * 64 * DH;
        const uint32_t s0 = sb + s * ASTAGE_B;
#pragma unroll
        for (int h = 0; h < 2; h++) {
            int c = tid + h * 256;
            int r = c >> 3, k8 = c & 7;
            uint32_t so = r * 144 + k8 * 16;
            size_t gg = gbase + r * 64 + k8 * 8;
            CP16(s0 + 0 * ATILE_B + so, g_Kh + gg);
            CP16(s0 + 1 * ATILE_B + so, g_Kl + gg);
            CP16(s0 + 2 * ATILE_B + so, g_Vh + gg);
            CP16(s0 + 3 * ATILE_B + so, g_Vl + gg);
        }
    };

    issue(0, 0); CPCOMMIT();

    float O[8][4] = {};
    float mr0 = -1e30f, mr1 = -1e30f, lw0 = 0.f, lw1 = 0.f;
    int stage = 0;

    const uint32_t bRow = (lane & 7) + ((lane >> 4) << 3);       // K frag rows
    const uint32_t bCs  = (lane >> 3) & 1;                       // K chunk sel
    const uint32_t vRow = (lane & 7) + (((lane >> 3) & 1) << 3); // V frag rows
    const uint32_t vCs  = lane >> 4;                             // V chunk sel

    for (int jt = 0; jt < TT / 64; jt++) {
        if (jt + 1 < TT / 64) { issue(jt + 1, stage ^ 1); CPCOMMIT(); CPWAIT(1); }
        else                  { CPWAIT(0); }
        __syncthreads();
        const uint32_t s0 = sb + stage * ASTAGE_B;
        const uint32_t sKh = s0, sKl = s0 + ATILE_B;
        const uint32_t sVh = s0 + 2 * ATILE_B, sVl = s0 + 3 * ATILE_B;

        // ---- S = Q @ K^T (3-term split), log2 units ----
        float Cs[8][4] = {};
#pragma unroll
        for (int ks = 0; ks < 4; ks++) {
#pragma unroll
            for (int nt = 0; nt < 4; nt++) {
                uint32_t off = (16 * nt + bRow) * 144 + (2 * ks + bCs) * 16;
                uint32_t kh4[4], kl4[4];
                ldmx4(kh4, sKh + off);
                ldmx4(kl4, sKl + off);
                mma16816(Cs[2 * nt],     aQh[ks], &kh4[0]);
                mma16816(Cs[2 * nt],     aQh[ks], &kl4[0]);
                mma16816(Cs[2 * nt],     aQl[ks], &kh4[0]);
                mma16816(Cs[2 * nt + 1], aQh[ks], &kh4[2]);
                mma16816(Cs[2 * nt + 1], aQh[ks], &kl4[2]);
                mma16816(Cs[2 * nt + 1], aQl[ks], &kh4[2]);
            }
        }

        // ---- mask + online softmax (base 2) ----
        float mx0 = -1e30f, mx1 = -1e30f;
#pragma unroll
        for (int t = 0; t < 8; t++) {
            float2 mk = *(const float2*)&mskf[jt * 64 + 8 * t + 2 * (lane & 3)];
            Cs[t][0] += mk.x; Cs[t][1] += mk.y;
            Cs[t][2] += mk.x; Cs[t][3] += mk.y;
            mx0 = fmaxf(mx0, fmaxf(Cs[t][0], Cs[t][1]));
            mx1 = fmaxf(mx1, fmaxf(Cs[t][2], Cs[t][3]));
        }
        mx0 = fmaxf(mx0, __shfl_xor_sync(0xffffffffu, mx0, 1));
        mx0 = fmaxf(mx0, __shfl_xor_sync(0xffffffffu, mx0, 2));
        mx1 = fmaxf(mx1, __shfl_xor_sync(0xffffffffu, mx1, 1));
        mx1 = fmaxf(mx1, __shfl_xor_sync(0xffffffffu, mx1, 2));
        float mn0 = fmaxf(mr0, mx0), mn1 = fmaxf(mr1, mx1);
        float2 alp = fexp2x2(mr0 - mn0, mr1 - mn1);
        float al0 = alp.x, al1 = alp.y;

        uint32_t ph0[8], ph1[8], pl0[8], pl1[8];
        float sum0 = 0.f, sum1 = 0.f;
#pragma unroll
        for (int t = 0; t < 8; t++) {
            float2 p01 = fexp2x2(Cs[t][0] - mn0, Cs[t][1] - mn0);
            float2 p23 = fexp2x2(Cs[t][2] - mn1, Cs[t][3] - mn1);
            sum0 += p01.x + p01.y; sum1 += p23.x + p23.y;
            __nv_bfloat162 h01 = __floats2bfloat162_rn(p01.x, p01.y);
            __nv_bfloat162 h23 = __floats2bfloat162_rn(p23.x, p23.y);
            float2 f01 = __bfloat1622float2(h01);
            float2 f23 = __bfloat1622float2(h23);
            __nv_bfloat162 l01 = __floats2bfloat162_rn(p01.x - f01.x, p01.y - f01.y);
            __nv_bfloat162 l23 = __floats2bfloat162_rn(p23.x - f23.x, p23.y - f23.y);
            ph0[t] = *(uint32_t*)&h01; ph1[t] = *(uint32_t*)&h23;
            pl0[t] = *(uint32_t*)&l01; pl1[t] = *(uint32_t*)&l23;
        }
        sum0 += __shfl_xor_sync(0xffffffffu, sum0, 1);
        sum0 += __shfl_xor_sync(0xffffffffu, sum0, 2);
        sum1 += __shfl_xor_sync(0xffffffffu, sum1, 1);
        sum1 += __shfl_xor_sync(0xffffffffu, sum1, 2);
        lw0 = lw0 * al0 + sum0;  lw1 = lw1 * al1 + sum1;
        mr0 = mn0;  mr1 = mn1;

        // ---- O = O*alpha + P @ V (3-term split) ----
#pragma unroll
        for (int dt = 0; dt < 8; dt++) {
            O[dt][0] *= al0; O[dt][1] *= al0;
            O[dt][2] *= al1; O[dt][3] *= al1;
        }
#pragma unroll
        for (int j = 0; j < 4; j++) {
            uint32_t Ahh[4] = { ph0[2 * j], ph1[2 * j], ph0[2 * j + 1], ph1[2 * j + 1] };
            uint32_t All[4] = { pl0[2 * j], pl1[2 * j], pl0[2 * j + 1], pl1[2 * j + 1] };
#pragma unroll
            for (int dp = 0; dp < 4; dp++) {
                uint32_t off = (16 * j + vRow) * 144 + (2 * dp + vCs) * 16;
                uint32_t vh4[4], vl4[4];
                ldmx4t(vh4, sVh + off);
                ldmx4t(vl4, sVl + off);
                mma16816(O[2 * dp],     Ahh, &vh4[0]);
                mma16816(O[2 * dp],     Ahh, &vl4[0]);
                mma16816(O[2 * dp],     All, &vh4[0]);
                mma16816(O[2 * dp + 1], Ahh, &vh4[2]);
                mma16816(O[2 * dp + 1], Ahh, &vl4[2]);
                mma16816(O[2 * dp + 1], All, &vh4[2]);
            }
        }
        __syncthreads();
        stage ^= 1;
    }

    // ---- epilogue: normalize, write bf16 hi/lo att in [B,T,H*Dh] ----------
    float inv0 = 1.0f / lw0, inv1 = 1.0f / lw1;
    const int t_lo = q0 + 16 * w + (lane >> 2);
    const size_t m_lo = (size_t)b * TT + t_lo;
#pragma unroll
    for (int dt = 0; dt < 8; dt++) {
        const int col = head * 64 + 8 * dt + 2 * (lane & 3);
#pragma unroll
        for (int hrow = 0; hrow < 2; hrow++) {
            const size_t idx = (m_lo + hrow * 8) * DM + col;
            float v0 = O[dt][2 * hrow + 0] * (hrow ? inv1 : inv0);
            float v1 = O[dt][2 * hrow + 1] * (hrow ? inv1 : inv0);
            __nv_bfloat162 h2 = __floats2bfloat162_rn(v0, v1);
            float2 hf = __bfloat1622float2(h2);
            __nv_bfloat162 l2 = __floats2bfloat162_rn(v0 - hf.x, v1 - hf.y);
            *(__nv_bfloat162*)(g_ath + idx) = h2;
            *(__nv_bfloat162*)(g_atl + idx) = l2;
        }
    }
}

// ---------------------------------------------------------------------------
// Inputs (metadata order): x, w_qkv, b_qkv, w_out, b_out, mask. Output: float32.
// ---------------------------------------------------------------------------
extern "C" void kernel_launch(void* const* d_in, const int* in_sizes, int n_in,
                              void* d_out, int out_size) {
    const float* x     = (const float*)d_in[0];
    const float* w_qkv = (const float*)d_in[1];
    const float* b_qkv = (const float*)d_in[2];
    const float* w_out = (const float*)d_in[3];
    const float* b_out = (const float*)d_in[4];
    const int*   mask  = (const int*)d_in[5];
    float* out = (float*)d_out;

    cudaFuncSetAttribute(gemm_mma<0>, cudaFuncAttributeMaxDynamicSharedMemorySize,
                         GEMM_SMEM);
    cudaFuncSetAttribute(gemm_mma<1>, cudaFuncAttributeMaxDynamicSharedMemorySize,
                         GEMM_SMEM);
    cudaFuncSetAttribute(attn_mma, cudaFuncAttributeMaxDynamicSharedMemorySize,
                         ATT_SMEM);

    __nv_bfloat16 *xh, *xl, *wqh, *wql, *woh, *wol, *ath, *atl;
    cudaGetSymbolAddress((void**)&xh,  g_xh);
    cudaGetSymbolAddress((void**)&xl,  g_xl);
    cudaGetSymbolAddress((void**)&wqh, g_wqh);
    cudaGetSymbolAddress((void**)&wql, g_wql);
    cudaGetSymbolAddress((void**)&woh, g_woh);
    cudaGetSymbolAddress((void**)&wol, g_wol);
    cudaGetSymbolAddress((void**)&ath, g_ath);
    cudaGetSymbolAddress((void**)&atl, g_atl);

    int nx = MTOT * DM / 2, nq = 3 * DM * DM / 2, no = DM * DM / 2;
    split_kernel<<<(nx + 255) / 256, 256>>>(x, (__nv_bfloat162*)xh,
                                            (__nv_bfloat162*)xl, nx);
    split_kernel<<<(nq + 255) / 256, 256>>>(w_qkv, (__nv_bfloat162*)wqh,
                                            (__nv_bfloat162*)wql, nq);
    split_kernel<<<(no + 255) / 256, 256>>>(w_out, (__nv_bfloat162*)woh,
                                            (__nv_bfloat162*)wol, no);

    // QKV projection (HMMA) -> bf16 hi/lo Q/K/V scratch
    gemm_mma<0><<<dim3(3 * DM / 128, MTOT / 128), 256, GEMM_SMEM>>>(
        xh, xl, wqh, wql, b_qkv, nullptr);

    // flash attention (HMMA + packed exp2 softmax, K-tile 64, 2 CTA/SM)
    attn_mma<<<dim3(TT / 128, BH), 256, ATT_SMEM>>>(mask);

    // out projection (HMMA)
    gemm_mma<1><<<dim3(DM / 128, MTOT / 128), 256, GEMM_SMEM>>>(
        ath, atl, woh, wol, b_out, out);
}

// round 14
// speedup vs baseline: 2.8858x; 1.0154x over previous
#include <cuda_runtime.h>
#include <cuda_bf16.h>
#include <cstdint>

#define DM   768
#define NH   12
#define DH   64
#define BB   2
#define TT   4096
#define BH   (BB*NH)
#define MTOT (BB*TT)        // 8192

typedef unsigned long long u64;

// Q pre-scale: 1/sqrt(64) * log2(e)  -> logits accumulate in log2 units
#define QSCALE 0.1803368801111204f

// ---------------- scratch (__device__ globals; no cudaMalloc allowed) ------
__device__ __align__(256) __nv_bfloat16 g_Qh[(size_t)BH*TT*DH];
__device__ __align__(256) __nv_bfloat16 g_Ql[(size_t)BH*TT*DH];
__device__ __align__(256) __nv_bfloat16 g_Kh[(size_t)BH*TT*DH];
__device__ __align__(256) __nv_bfloat16 g_Kl[(size_t)BH*TT*DH];
__device__ __align__(256) __nv_bfloat16 g_Vh[(size_t)BH*TT*DH];
__device__ __align__(256) __nv_bfloat16 g_Vl[(size_t)BH*TT*DH];

__device__ __align__(256) __nv_bfloat16 g_xh[(size_t)MTOT*DM];
__device__ __align__(256) __nv_bfloat16 g_xl[(size_t)MTOT*DM];
__device__ __align__(256) __nv_bfloat16 g_wqh[(size_t)3*DM*DM];
__device__ __align__(256) __nv_bfloat16 g_wql[(size_t)3*DM*DM];
__device__ __align__(256) __nv_bfloat16 g_woh[(size_t)DM*DM];
__device__ __align__(256) __nv_bfloat16 g_wol[(size_t)DM*DM];
__device__ __align__(256) __nv_bfloat16 g_ath[(size_t)MTOT*DM];
__device__ __align__(256) __nv_bfloat16 g_atl[(size_t)MTOT*DM];

// ---------------- PTX helpers (sm_80-era: legal on plain sm_103) -----------
__device__ __forceinline__ uint32_t smem_u32(const void* p) {
    uint32_t a;
    asm("{ .reg .u64 t; cvta.to.shared.u64 t, %1; cvt.u32.u64 %0, t; }"
        : "=r"(a) : "l"(p));
    return a;
}
__device__ __forceinline__ void ldmx4(uint32_t* r, uint32_t addr) {
    asm volatile("ldmatrix.sync.aligned.m8n8.x4.shared.b16 {%0,%1,%2,%3}, [%4];"
                 : "=r"(r[0]), "=r"(r[1]), "=r"(r[2]), "=r"(r[3]) : "r"(addr));
}
__device__ __forceinline__ void ldmx4t(uint32_t* r, uint32_t addr) {
    asm volatile("ldmatrix.sync.aligned.m8n8.x4.trans.shared.b16 {%0,%1,%2,%3}, [%4];"
                 : "=r"(r[0]), "=r"(r[1]), "=r"(r[2]), "=r"(r[3]) : "r"(addr));
}
__device__ __forceinline__ void mma16816(float* c, const uint32_t* a,
                                         const uint32_t* b) {
    asm volatile(
        "mma.sync.aligned.m16n8k16.row.col.f32.bf16.bf16.f32 "
        "{%0,%1,%2,%3}, {%4,%5,%6,%7}, {%8,%9}, {%0,%1,%2,%3};"
        : "+f"(c[0]), "+f"(c[1]), "+f"(c[2]), "+f"(c[3])
        : "r"(a[0]), "r"(a[1]), "r"(a[2]), "r"(a[3]), "r"(b[0]), "r"(b[1]));
}
#define CP16(saddr, gptr) \
    asm volatile("cp.async.cg.shared.global [%0], [%1], 16;" \
                 :: "r"(saddr), "l"(gptr))
#define CPCOMMIT() asm volatile("cp.async.commit_group;" ::: "memory")
#define CPWAIT(n)  asm volatile("cp.async.wait_group %0;" :: "n"(n) : "memory")

// ---- packed f32x2 helpers ----
__device__ __forceinline__ u64 pack2(float lo, float hi) {
    u64 r; asm("mov.b64 %0,{%1,%2};" : "=l"(r) : "f"(lo), "f"(hi)); return r;
}
__device__ __forceinline__ void unpack2(u64 v, float& lo, float& hi) {
    asm("mov.b64 {%0,%1},%2;" : "=f"(lo), "=f"(hi) : "l"(v));
}
__device__ __forceinline__ u64 add2(u64 a, u64 b) {
    u64 d; asm("add.rn.f32x2 %0,%1,%2;" : "=l"(d) : "l"(a), "l"(b)); return d;
}
__device__ __forceinline__ u64 fma2v(u64 a, u64 b, u64 c) {
    u64 d; asm("fma.rn.f32x2 %0,%1,%2,%3;" : "=l"(d) : "l"(a), "l"(b), "l"(c));
    return d;
}

// MUFU-free packed exp2: magic round + degree-6 poly of 2^f, f in [-0.5,0.5].
// Inputs MUST be <= 0 (softmax-shifted). rel err ~2e-7.
__device__ __forceinline__ float2 fexp2x2(float a, float b) {
    a = fmaxf(a, -120.0f);
    b = fmaxf(b, -120.0f);
    const u64 C2   = pack2(12582912.0f, 12582912.0f);   // 1.5*2^23
    const u64 nC2  = pack2(-12582912.0f, -12582912.0f);
    const u64 m1   = pack2(-1.0f, -1.0f);
    u64 y = pack2(a, b);
    u64 t = add2(y, C2);
    float t0, t1; unpack2(t, t0, t1);
    int n0 = __float_as_int(t0) - 0x4B400000;
    int n1 = __float_as_int(t1) - 0x4B400000;
    u64 t2 = add2(t, nC2);
    u64 f  = fma2v(t2, m1, y);                          // f = y - round(y)
    u64 p  = pack2(1.5403530e-4f, 1.5403530e-4f);
    p = fma2v(p, f, pack2(1.3333558e-3f, 1.3333558e-3f));
    p = fma2v(p, f, pack2(9.6181291e-3f, 9.6181291e-3f));
    p = fma2v(p, f, pack2(5.5504109e-2f, 5.5504109e-2f));
    p = fma2v(p, f, pack2(2.4022651e-1f, 2.4022651e-1f));
    p = fma2v(p, f, pack2(6.9314718e-1f, 6.9314718e-1f));
    p = fma2v(p, f, pack2(1.0f, 1.0f));
    float p0, p1; unpack2(p, p0, p1);
    float2 r;
    r.x = __int_as_float(__float_as_int(p0) + (n0 << 23));
    r.y = __int_as_float(__float_as_int(p1) + (n1 << 23));
    return r;
}

// ---------------- fp32 -> bf16 hi/lo split ----------------------------------
__global__ __launch_bounds__(256) void split_kernel(const float* __restrict__ in,
                                                    __nv_bfloat162* __restrict__ hi,
                                                    __nv_bfloat162* __restrict__ lo,
                                                    int n2) {
    int i = blockIdx.x * 256 + threadIdx.x;
    if (i < n2) {
        float2 v = ((const float2*)in)[i];
        __nv_bfloat16 hx = __float2bfloat16(v.x);
        __nv_bfloat16 hy = __float2bfloat16(v.y);
        float rx = v.x - __bfloat162float(hx);
        float ry = v.y - __bfloat162float(hy);
        hi[i] = __halves2bfloat162(hx, hy);
        lo[i] = __halves2bfloat162(__float2bfloat16(rx), __float2bfloat16(ry));
    }
}

// ---------------- HMMA GEMM: C = A @ B^T (+bias) ----------------------------
// MODE 0: qkv -> scatter bf16 hi/lo into g_Q*/g_K*/g_V* (Q scaled by QSCALE).
// MODE 1: out -> fp32 dst[m*768+n].
#define KT       32
#define SSTRIDE  40
#define TILE_B   (128 * SSTRIDE * 2)
#define STAGE_B  (4 * TILE_B)
#define GEMM_SMEM (2 * STAGE_B)

template <int MODE>
__global__ __launch_bounds__(256, 2) void gemm_mma(const __nv_bfloat16* __restrict__ Ah,
                                                   const __nv_bfloat16* __restrict__ Al,
                                                   const __nv_bfloat16* __restrict__ Bh,
                                                   const __nv_bfloat16* __restrict__ Bl,
                                                   const float* __restrict__ bias,
                                                   float* __restrict__ dst) {
    extern __shared__ char smem[];
    const uint32_t sb = smem_u32(smem);
    const int tid = threadIdx.x, wid = tid >> 5, lane = tid & 31;
    const int n0 = blockIdx.x * 128, m0 = blockIdx.y * 128;
    const int wm = wid & 1, wn = wid >> 1;

    const int r_ld[2]  = { (tid + 0)   >> 2, (tid + 256) >> 2 };
    const int c8_ld[2] = { (tid + 0) & 3,    (tid + 256) & 3 };

    auto issue = [&](int kt, int stage) {
        const int k0 = kt * KT;
        const uint32_t s0 = sb + stage * STAGE_B;
#pragma unroll
        for (int h = 0; h < 2; h++) {
            const int r = r_ld[h], c8 = c8_ld[h];
            const uint32_t so = (uint32_t)(r * (SSTRIDE * 2) + c8 * 16);
            const size_t ga = (size_t)(m0 + r) * DM + k0 + c8 * 8;
            const size_t gb = (size_t)(n0 + r) * DM + k0 + c8 * 8;
            CP16(s0 + 0 * TILE_B + so, Ah + ga);
            CP16(s0 + 1 * TILE_B + so, Al + ga);
            CP16(s0 + 2 * TILE_B + so, Bh + gb);
            CP16(s0 + 3 * TILE_B + so, Bl + gb);
        }
    };

    float C[4][4][4] = {};

    issue(0, 0);
    CPCOMMIT();
    int stage = 0;
    const int NKT = DM / KT;
    for (int kt = 0; kt < NKT; kt++) {
        if (kt + 1 < NKT) { issue(kt + 1, stage ^ 1); CPCOMMIT(); CPWAIT(1); }
        else              { CPWAIT(0); }
        __syncthreads();

        const uint32_t s0 = sb + stage * STAGE_B;
        const uint32_t aRow = (uint32_t)(wm * 64 + (lane & 15));
        const uint32_t aK   = (uint32_t)((lane >> 4) * 8);
        const uint32_t bRow = (uint32_t)(wn * 32 + (lane & 7) + ((lane >> 4) & 1) * 8);
        const uint32_t bK   = (uint32_t)(((lane >> 3) & 1) * 8);
#pragma unroll
        for (int s = 0; s < 2; s++) {
            uint32_t ah[4][4], al[4][4], bh[2][4], bl[2][4];
#pragma unroll
            for (int mt = 0; mt < 4; mt++) {
                uint32_t off = (aRow + mt * 16) * (SSTRIDE * 2) + (aK + s * 16) * 2;
                ldmx4(ah[mt], s0 + 0 * TILE_B + off);
                ldmx4(al[mt], s0 + 1 * TILE_B + off);
            }
#pragma unroll
            for (int nt = 0; nt < 2; nt++) {
                uint32_t off = (bRow + nt * 16) * (SSTRIDE * 2) + (bK + s * 16) * 2;
                ldmx4(bh[nt], s0 + 2 * TILE_B + off);
                ldmx4(bl[nt], s0 + 3 * TILE_B + off);
            }
#pragma unroll
            for (int mt = 0; mt < 4; mt++) {
#pragma unroll
                for (int nt = 0; nt < 2; nt++) {
#pragma unroll
                    for (int ns = 0; ns < 2; ns++) {
                        float* c = C[mt][nt * 2 + ns];
                        mma16816(c, ah[mt], &bh[nt][ns * 2]);
                        mma16816(c, ah[mt], &bl[nt][ns * 2]);
                        mma16816(c, al[mt], &bh[nt][ns * 2]);
                    }
                }
            }
        }
        __syncthreads();
        stage ^= 1;
    }

    const int g = lane >> 2, tg = lane & 3;
#pragma unroll
    for (int mt = 0; mt < 4; mt++) {
#pragma unroll
        for (int n8 = 0; n8 < 4; n8++) {
            const int col = n0 + wn * 32 + n8 * 8 + 2 * tg;
            const int row = m0 + wm * 64 + mt * 16 + g;
            const float b0 = bias[col], b1 = bias[col + 1];
            float* c = C[mt][n8];
            if (MODE == 0) {
                const int which = col / DM;
                const int hd = (col % DM) >> 6;
                const int d0 = col & 63;
                __nv_bfloat16 *dph, *dpl;
                if (which == 0)      { dph = g_Qh; dpl = g_Ql; }
                else if (which == 1) { dph = g_Kh; dpl = g_Kl; }
                else                 { dph = g_Vh; dpl = g_Vl; }
                const float sc = (which == 0) ? QSCALE : 1.0f;
#pragma unroll
                for (int hrow = 0; hrow < 2; hrow++) {
                    const int m = row + hrow * 8;
                    const int bb = m >> 12, t = m & 4095;
                    const size_t idx = (((size_t)(bb * NH + hd)) * TT + t) * DH + d0;
                    float v0 = (c[2 * hrow + 0] + b0) * sc;
                    float v1 = (c[2 * hrow + 1] + b1) * sc;
                    __nv_bfloat162 h2 = __floats2bfloat162_rn(v0, v1);
                    float2 hf = __bfloat1622float2(h2);
                    __nv_bfloat162 l2 = __floats2bfloat162_rn(v0 - hf.x, v1 - hf.y);
                    *(__nv_bfloat162*)(dph + idx) = h2;
                    *(__nv_bfloat162*)(dpl + idx) = l2;
                }
            } else {
#pragma unroll
                for (int hrow = 0; hrow < 2; hrow++) {
                    const int m = row + hrow * 8;
                    float2 v;
                    v.x = c[2 * hrow + 0] + b0;
                    v.y = c[2 * hrow + 1] + b1;
                    *(float2*)(dst + (size_t)m * DM + col) = v;
                }
            }
        }
    }
}

// ---------------- HMMA flash attention --------------------------------------
// CTA = 128 q-rows x one (b,h); 4 warps, each owns 32 q-rows (two 16-row
// blocks) so every K/V ldmatrix feeds 2x the MMAs (halved LDS traffic).
// K-tile 64 (smem 88 KB -> 2 CTAs/SM). Logits in log2 units -> exp2 softmax.
#define AST      72                       // bf16 stride (144 B rows)
#define ATILE_B  (64 * AST * 2)           // 9216 B per tensor tile (64 rows)
#define ASTAGE_B (4 * ATILE_B)            // K/V hi/lo = 36864 B
#define AMASK_OFF (2 * ASTAGE_B)          // 73728
#define ATT_SMEM  (AMASK_OFF + TT * 4)    // +16 KB mask floats = 90112

__global__ __launch_bounds__(128, 2) void attn_mma(const int* __restrict__ mask) {
    extern __shared__ char smraw[];
    const uint32_t sb = smem_u32(smraw);
    float* mskf = (float*)(smraw + AMASK_OFF);

    const int tid = threadIdx.x, w = tid >> 5, lane = tid & 31;
    const int bh = blockIdx.y, b = bh / NH, head = bh % NH;
    const int q0 = blockIdx.x * 128;
    const size_t kvbase = (size_t)bh * TT * DH;

    // mask -> additive floats (log2 units; -1e9 is still -inf-ish)
    for (int i = tid; i < TT / 4; i += 128) {
        int4 mm = ((const int4*)(mask + (size_t)b * TT))[i];
        float4 f;
        f.x = mm.x ? 0.f : -1e9f; f.y = mm.y ? 0.f : -1e9f;
        f.z = mm.z ? 0.f : -1e9f; f.w = mm.w ? 0.f : -1e9f;
        ((float4*)mskf)[i] = f;
    }

    // stage Q (hi/lo: 128 rows each = 18432 B each) across stage-0 region
    {
        const size_t qb = kvbase + (size_t)q0 * DH;
#pragma unroll
        for (int h = 0; h < 8; h++) {
            int c = tid + h * 128;
            int r = c >> 3, k8 = c & 7;
            uint32_t so = r * 144 + k8 * 16;
            CP16(sb + so,                g_Qh + qb + r * 64 + k8 * 8);
            CP16(sb + 2 * ATILE_B + so,  g_Ql + qb + r * 64 + k8 * 8);
        }
        CPCOMMIT(); CPWAIT(0);
    }
    __syncthreads();
    uint32_t aQh[2][4][4], aQl[2][4][4];
#pragma unroll
    for (int rb = 0; rb < 2; rb++) {
        uint32_t row = 32 * w + 16 * rb + (lane & 15);
#pragma unroll
        for (int ks = 0; ks < 4; ks++) {
            uint32_t off = row * 144 + (2 * ks + (lane >> 4)) * 16;
            ldmx4(aQh[rb][ks], sb + off);
            ldmx4(aQl[rb][ks], sb + 2 * ATILE_B + off);
        }
    }
    __syncthreads();

    auto issue = [&](int jt, int s) {
        const size_t gbase = kvbase + (size_t)jt * 64 * DH;
        const uint32_t s0 = sb + s * ASTAGE_B;
#pragma unroll
        for (int h = 0; h < 4; h++) {
            int c = tid + h * 128;
            int r = c >> 3, k8 = c & 7;
            uint32_t so = r * 144 + k8 * 16;
            size_t gg = gbase + r * 64 + k8 * 8;
            CP16(s0 + 0 * ATILE_B + so, g_Kh + gg);
            CP16(s0 + 1 * ATILE_B + so, g_Kl + gg);
            CP16(s0 + 2 * ATILE_B + so, g_Vh + gg);
            CP16(s0 + 3 * ATILE_B + so, g_Vl + gg);
        }
    };

    issue(0, 0); CPCOMMIT();

    float O[2][8][4] = {};
    float mr[2][2], lw[2][2];
#pragma unroll
    for (int rb = 0; rb < 2; rb++) {
        mr[rb][0] = -1e30f; mr[rb][1] = -1e30f;
        lw[rb][0] = 0.f;    lw[rb][1] = 0.f;
    }
    int stage = 0;

    const uint32_t bRow = (lane & 7) + ((lane >> 4) << 3);       // K frag rows
    const uint32_t bCs  = (lane >> 3) & 1;                       // K chunk sel
    const uint32_t vRow = (lane & 7) + (((lane >> 3) & 1) << 3); // V frag rows
    const uint32_t vCs  = lane >> 4;                             // V chunk sel

    for (int jt = 0; jt < TT / 64; jt++) {
        if (jt + 1 < TT / 64) { issue(jt + 1, stage ^ 1); CPCOMMIT(); CPWAIT(1); }
        else                  { CPWAIT(0); }
        __syncthreads();
        const uint32_t s0 = sb + stage * ASTAGE_B;
        const uint32_t sKh = s0, sKl = s0 + ATILE_B;
        const uint32_t sVh = s0 + 2 * ATILE_B, sVl = s0 + 3 * ATILE_B;

        // ---- S = Q @ K^T (3-term split), log2 units; K frags shared by both
        //      16-row blocks of this warp ----
        float Cs[2][8][4] = {};
#pragma unroll
        for (int ks = 0; ks < 4; ks++) {
#pragma unroll
            for (int nt = 0; nt < 4; nt++) {
                uint32_t off = (16 * nt + bRow) * 144 + (2 * ks + bCs) * 16;
                uint32_t kh4[4], kl4[4];
                ldmx4(kh4, sKh + off);
                ldmx4(kl4, sKl + off);
#pragma unroll
                for (int rb = 0; rb < 2; rb++) {
                    mma16816(Cs[rb][2 * nt],     aQh[rb][ks], &kh4[0]);
                    mma16816(Cs[rb][2 * nt],     aQh[rb][ks], &kl4[0]);
                    mma16816(Cs[rb][2 * nt],     aQl[rb][ks], &kh4[0]);
                    mma16816(Cs[rb][2 * nt + 1], aQh[rb][ks], &kh4[2]);
                    mma16816(Cs[rb][2 * nt + 1], aQh[rb][ks], &kl4[2]);
                    mma16816(Cs[rb][2 * nt + 1], aQl[rb][ks], &kh4[2]);
                }
            }
        }

        // ---- mask + online softmax (base 2), per row-block ----
        uint32_t ph0[2][8], ph1[2][8], pl0[2][8], pl1[2][8];
        float al[2][2];
#pragma unroll
        for (int rb = 0; rb < 2; rb++) {
            float mx0 = -1e30f, mx1 = -1e30f;
#pragma unroll
            for (int t = 0; t < 8; t++) {
                float2 mk = *(const float2*)&mskf[jt * 64 + 8 * t + 2 * (lane & 3)];
                Cs[rb][t][0] += mk.x; Cs[rb][t][1] += mk.y;
                Cs[rb][t][2] += mk.x; Cs[rb][t][3] += mk.y;
                mx0 = fmaxf(mx0, fmaxf(Cs[rb][t][0], Cs[rb][t][1]));
                mx1 = fmaxf(mx1, fmaxf(Cs[rb][t][2], Cs[rb][t][3]));
            }
            mx0 = fmaxf(mx0, __shfl_xor_sync(0xffffffffu, mx0, 1));
            mx0 = fmaxf(mx0, __shfl_xor_sync(0xffffffffu, mx0, 2));
            mx1 = fmaxf(mx1, __shfl_xor_sync(0xffffffffu, mx1, 1));
            mx1 = fmaxf(mx1, __shfl_xor_sync(0xffffffffu, mx1, 2));
            float mn0 = fmaxf(mr[rb][0], mx0), mn1 = fmaxf(mr[rb][1], mx1);
            float2 alp = fexp2x2(mr[rb][0] - mn0, mr[rb][1] - mn1);
            al[rb][0] = alp.x; al[rb][1] = alp.y;

            float sum0 = 0.f, sum1 = 0.f;
#pragma unroll
            for (int t = 0; t < 8; t++) {
                float2 p01 = fexp2x2(Cs[rb][t][0] - mn0, Cs[rb][t][1] - mn0);
                float2 p23 = fexp2x2(Cs[rb][t][2] - mn1, Cs[rb][t][3] - mn1);
                sum0 += p01.x + p01.y; sum1 += p23.x + p23.y;
                __nv_bfloat162 h01 = __floats2bfloat162_rn(p01.x, p01.y);
                __nv_bfloat162 h23 = __floats2bfloat162_rn(p23.x, p23.y);
                float2 f01 = __bfloat1622float2(h01);
                float2 f23 = __bfloat1622float2(h23);
                __nv_bfloat162 l01 = __floats2bfloat162_rn(p01.x - f01.x, p01.y - f01.y);
                __nv_bfloat162 l23 = __floats2bfloat162_rn(p23.x - f23.x, p23.y - f23.y);
                ph0[rb][t] = *(uint32_t*)&h01; ph1[rb][t] = *(uint32_t*)&h23;
                pl0[rb][t] = *(uint32_t*)&l01; pl1[rb][t] = *(uint32_t*)&l23;
            }
            sum0 += __shfl_xor_sync(0xffffffffu, sum0, 1);
            sum0 += __shfl_xor_sync(0xffffffffu, sum0, 2);
            sum1 += __shfl_xor_sync(0xffffffffu, sum1, 1);
            sum1 += __shfl_xor_sync(0xffffffffu, sum1, 2);
            lw[rb][0] = lw[rb][0] * al[rb][0] + sum0;
            lw[rb][1] = lw[rb][1] * al[rb][1] + sum1;
            mr[rb][0] = mn0;  mr[rb][1] = mn1;
        }

        // ---- O = O*alpha + P @ V (3-term split); V frags shared by blocks --
#pragma unroll
        for (int rb = 0; rb < 2; rb++)
#pragma unroll
            for (int dt = 0; dt < 8; dt++) {
                O[rb][dt][0] *= al[rb][0]; O[rb][dt][1] *= al[rb][0];
                O[rb][dt][2] *= al[rb][1]; O[rb][dt][3] *= al[rb][1];
            }
#pragma unroll
        for (int j = 0; j < 4; j++) {
            uint32_t Ahh[2][4], All[2][4];
#pragma unroll
            for (int rb = 0; rb < 2; rb++) {
                Ahh[rb][0] = ph0[rb][2 * j];     Ahh[rb][1] = ph1[rb][2 * j];
                Ahh[rb][2] = ph0[rb][2 * j + 1]; Ahh[rb][3] = ph1[rb][2 * j + 1];
                All[rb][0] = pl0[rb][2 * j];     All[rb][1] = pl1[rb][2 * j];
                All[rb][2] = pl0[rb][2 * j + 1]; All[rb][3] = pl1[rb][2 * j + 1];
            }
#pragma unroll
            for (int dp = 0; dp < 4; dp++) {
                uint32_t off = (16 * j + vRow) * 144 + (2 * dp + vCs) * 16;
                uint32_t vh4[4], vl4[4];
                ldmx4t(vh4, sVh + off);
                ldmx4t(vl4, sVl + off);
#pragma unroll
                for (int rb = 0; rb < 2; rb++) {
                    mma16816(O[rb][2 * dp],     Ahh[rb], &vh4[0]);
                    mma16816(O[rb][2 * dp],     Ahh[rb], &vl4[0]);
                    mma16816(O[rb][2 * dp],     All[rb], &vh4[0]);
                    mma16816(O[rb][2 * dp + 1], Ahh[rb], &vh4[2]);
                    mma16816(O[rb][2 * dp + 1], Ahh[rb], &vl4[2]);
                    mma16816(O[rb][2 * dp + 1], All[rb], &vh4[2]);
                }
            }
        }
        __syncthreads();
        stage ^= 1;
    }

    // ---- epilogue: normalize, write bf16 hi/lo att in [B,T,H*Dh] ----------
#pragma unroll
    for (int rb = 0; rb < 2; rb++) {
        float inv0 = 1.0f / lw[rb][0], inv1 = 1.0f / lw[rb][1];
        const int t_lo = q0 + 32 * w + 16 * rb + (lane >> 2);
        const size_t m_lo = (size_t)b * TT + t_lo;
#pragma unroll
        for (int dt = 0; dt < 8; dt++) {
            const int col = head * 64 + 8 * dt + 2 * (lane & 3);
#pragma unroll
            for (int hrow = 0; hrow < 2; hrow++) {
                const size_t idx = (m_lo + hrow * 8) * DM + col;
                float v0 = O[rb][dt][2 * hrow + 0] * (hrow ? inv1 : inv0);
                float v1 = O[rb][dt][2 * hrow + 1] * (hrow ? inv1 : inv0);
                __nv_bfloat162 h2 = __floats2bfloat162_rn(v0, v1);
                float2 hf = __bfloat1622float2(h2);
                __nv_bfloat162 l2 = __floats2bfloat162_rn(v0 - hf.x, v1 - hf.y);
                *(__nv_bfloat162*)(g_ath + idx) = h2;
                *(__nv_bfloat162*)(g_atl + idx) = l2;
            }
        }
    }
}

// ---------------------------------------------------------------------------
// Inputs (metadata order): x, w_qkv, b_qkv, w_out, b_out, mask. Output: float32.
// ---------------------------------------------------------------------------
extern "C" void kernel_launch(void* const* d_in, const int* in_sizes, int n_in,
                              void* d_out, int out_size) {
    const float* x     = (const float*)d_in[0];
    const float* w_qkv = (const float*)d_in[1];
    const float* b_qkv = (const float*)d_in[2];
    const float* w_out = (const float*)d_in[3];
    const float* b_out = (const float*)d_in[4];
    const int*   mask  = (const int*)d_in[5];
    float* out = (float*)d_out;

    cudaFuncSetAttribute(gemm_mma<0>, cudaFuncAttributeMaxDynamicSharedMemorySize,
                         GEMM_SMEM);
    cudaFuncSetAttribute(gemm_mma<1>, cudaFuncAttributeMaxDynamicSharedMemorySize,
                         GEMM_SMEM);
    cudaFuncSetAttribute(attn_mma, cudaFuncAttributeMaxDynamicSharedMemorySize,
                         ATT_SMEM);

    __nv_bfloat16 *xh, *xl, *wqh, *wql, *woh, *wol, *ath, *atl;
    cudaGetSymbolAddress((void**)&xh,  g_xh);
    cudaGetSymbolAddress((void**)&xl,  g_xl);
    cudaGetSymbolAddress((void**)&wqh, g_wqh);
    cudaGetSymbolAddress((void**)&wql, g_wql);
    cudaGetSymbolAddress((void**)&woh, g_woh);
    cudaGetSymbolAddress((void**)&wol, g_wol);
    cudaGetSymbolAddress((void**)&ath, g_ath);
    cudaGetSymbolAddress((void**)&atl, g_atl);

    int nx = MTOT * DM / 2, nq = 3 * DM * DM / 2, no = DM * DM / 2;
    split_kernel<<<(nx + 255) / 256, 256>>>(x, (__nv_bfloat162*)xh,
                                            (__nv_bfloat162*)xl, nx);
    split_kernel<<<(nq + 255) / 256, 256>>>(w_qkv, (__nv_bfloat162*)wqh,
                                            (__nv_bfloat162*)wql, nq);
    split_kernel<<<(no + 255) / 256, 256>>>(w_out, (__nv_bfloat162*)woh,
                                            (__nv_bfloat162*)wol, no);

    // QKV projection (HMMA) -> bf16 hi/lo Q/K/V scratch
    gemm_mma<0><<<dim3(3 * DM / 128, MTOT / 128), 256, GEMM_SMEM>>>(
        xh, xl, wqh, wql, b_qkv, nullptr);

    // flash attention (HMMA, 4 warps x 32 q-rows, K-tile 64, 2 CTA/SM)
    attn_mma<<<dim3(TT / 128, BH), 128, ATT_SMEM>>>(mask);

    // out projection (HMMA)
    gemm_mma<1><<<dim3(DM / 128, MTOT / 128), 256, GEMM_SMEM>>>(
        ath, atl, woh, wol, b_out, out);
}